// round 13
// baseline (speedup 1.0000x reference)
#include <cuda_runtime.h>
#include <cuda_bf16.h>
#include <math.h>
#include <stdint.h>

// ---------------- constants ----------------
#define BATCH   256
#define SEQ     26
#define DMODEL  512
#define HEMB    256
#define NHEADS  8
#define NROWS   (BATCH*SEQ)     // 6656
#define NPATCH  25
#define CONVK   675             // 3*15*15
#define CONVKP  704             // padded to multiple of 64
#define NQKV    1792            // 512+512+512+256 fused projection width

typedef __nv_bfloat16 bf16;

// ---------------- scratch (device globals; no runtime allocation) ----------------
__device__ bf16  g_im2col[BATCH*NPATCH*CONVKP];
__device__ bf16  g_wc[HEMB*CONVKP];          // [N=256][K=704]
__device__ bf16  g_mapT[DMODEL*DMODEL];      // [N=512][K=512]
__device__ bf16  g_wqkv[NQKV*DMODEL];        // [N=1792][K=512]
__device__ bf16  g_finalT[DMODEL*DMODEL];
__device__ bf16  g_ffn1T[2*DMODEL*DMODEL];   // [N=1024][K=512]
__device__ bf16  g_ffn2T[DMODEL*2*DMODEL];   // [N=512][K=1024]
__device__ float g_bqkv[NQKV];
__device__ float g_pe[NPATCH*HEMB];
__device__ float g_pemb[BATCH*NPATCH*HEMB];
__device__ bf16  g_xin[NROWS*DMODEL];
__device__ float g_x[NROWS*DMODEL];
__device__ bf16  g_h[NROWS*DMODEL];
__device__ bf16  g_qkvb[NROWS*NQKV];         // bf16 qkv output
__device__ bf16  g_o[NROWS*DMODEL];
__device__ bf16  g_t[NROWS*2*DMODEL];

// ---------------- helpers ----------------
__device__ __forceinline__ uint32_t smem_u32(const void* p) {
    uint32_t a;
    asm("{ .reg .u64 t; cvta.to.shared.u64 t, %1; cvt.u32.u64 %0, t; }" : "=r"(a) : "l"(p));
    return a;
}
__device__ __forceinline__ void mma_bf16(float* d, const uint32_t* a, const uint32_t* b) {
    asm volatile(
        "mma.sync.aligned.m16n8k16.row.col.f32.bf16.bf16.f32 "
        "{%0,%1,%2,%3}, {%4,%5,%6,%7}, {%8,%9}, {%0,%1,%2,%3};"
        : "+f"(d[0]), "+f"(d[1]), "+f"(d[2]), "+f"(d[3])
        : "r"(a[0]), "r"(a[1]), "r"(a[2]), "r"(a[3]), "r"(b[0]), "r"(b[1]));
}
__device__ __forceinline__ void ldmatrix_x4(uint32_t* r, uint32_t addr) {
    asm volatile("ldmatrix.sync.aligned.m8n8.x4.shared.b16 {%0,%1,%2,%3}, [%4];"
                 : "=r"(r[0]), "=r"(r[1]), "=r"(r[2]), "=r"(r[3]) : "r"(addr));
}
__device__ __forceinline__ void cp_async16(uint32_t dst, const void* src) {
    asm volatile("cp.async.cg.shared.global [%0], [%1], 16;" :: "r"(dst), "l"(src));
}
__device__ __forceinline__ float2 bf2_to_f2(uint32_t u) {
    __nv_bfloat162 h = *reinterpret_cast<__nv_bfloat162*>(&u);
    return __bfloat1622float2(h);
}
// packed f32x2 helpers (sm_103a FFMA2 path)
typedef unsigned long long u64t;
__device__ __forceinline__ u64t pack_ff(float lo, float hi) {
    u64t r;
    asm("mov.b64 %0, {%1, %2};" : "=l"(r) : "f"(lo), "f"(hi));
    return r;
}
__device__ __forceinline__ void fma_x2(u64t& d, u64t a, u64t b) {
    asm("fma.rn.f32x2 %0, %1, %2, %3;" : "=l"(d) : "l"(a), "l"(b), "l"(d));
}
__device__ __forceinline__ float2 unpack_ff(u64t v) {
    float lo, hi;
    asm("mov.b64 {%0, %1}, %2;" : "=f"(lo), "=f"(hi) : "l"(v));
    return make_float2(lo, hi);
}
__device__ __forceinline__ u64t bf2_to_fx2(uint32_t u) {
    uint32_t lo = u << 16;
    uint32_t hi = u & 0xffff0000u;
    u64t r;
    asm("mov.b64 %0, {%1, %2};" : "=l"(r) : "r"(lo), "r"(hi));
    return r;
}

// ---------------- bf16 mma.sync GEMM, 64x128 tile, 2-stage cp.async, 3 CTAs/SM ----------------
// C[M,N] = epi(A[M,K]bf16 @ B[N,K]bf16^T + bias[N])
// mode 0: bias -> fp32 C   mode 1: bias+relu -> bf16 Cb
// mode 2: bias+Res -> fp32 C   mode 3: bias -> bf16 Cb
#define BM 64
#define BN 128
#define BK 64
#define TS 72
#define A_STAGE_BYTES (64 * TS * 2)      // 9216
#define B_STAGE_BYTES (128 * TS * 2)     // 18432
#define GEMM_SMEM_BYTES (2 * (A_STAGE_BYTES + B_STAGE_BYTES))   // 55296

__global__ void __launch_bounds__(256, 3) gemm_tc(
    const bf16* __restrict__ A, const bf16* __restrict__ B,
    const float* __restrict__ bias, const float* __restrict__ Res,
    float* __restrict__ C, bf16* __restrict__ Cb,
    int M, int N, int K, int mode)
{
    extern __shared__ bf16 smem[];
    const uint32_t as_u = smem_u32(smem);
    const uint32_t bs_u = as_u + 2 * A_STAGE_BYTES;

    const int bm = blockIdx.y * BM;
    const int bn = blockIdx.x * BN;
    const int tid = threadIdx.x;
    const int lane = tid & 31;
    const int wid = tid >> 5;
    const int wm = (wid & 1) * 32;
    const int wn = (wid >> 1) * 32;

    const int rbase = tid >> 3;
    const int kq = (tid & 7) << 3;
    const uint32_t sO = (uint32_t)(rbase * TS + kq) * 2;

    const bf16* pA = A + (size_t)(bm + rbase) * K + kq;
    const bf16* pB = B + (size_t)(bn + rbase) * K + kq;
    const size_t rowstep = (size_t)32 * K;

    float acc[2][4][4];
    #pragma unroll
    for (int mi = 0; mi < 2; mi++)
        #pragma unroll
        for (int ni = 0; ni < 4; ni++)
            #pragma unroll
            for (int r = 0; r < 4; r++) acc[mi][ni][r] = 0.0f;

    const int nchunks = K / BK;

#define ISSUE_STAGE(s)                                                   \
    do {                                                                 \
        const uint32_t ab = as_u + (uint32_t)(s) * A_STAGE_BYTES + sO;   \
        const uint32_t bb = bs_u + (uint32_t)(s) * B_STAGE_BYTES + sO;   \
        cp_async16(ab,         pA);                                      \
        cp_async16(ab + 4608,  pA + rowstep);                            \
        cp_async16(bb,         pB);                                      \
        cp_async16(bb + 4608,  pB + rowstep);                            \
        cp_async16(bb + 9216,  pB + 2 * rowstep);                        \
        cp_async16(bb + 13824, pB + 3 * rowstep);                        \
        asm volatile("cp.async.commit_group;" ::: "memory");             \
        pA += BK; pB += BK;                                              \
    } while (0)

    ISSUE_STAGE(0);
    if (nchunks > 1) ISSUE_STAGE(1);

    const int a_row = (lane & 15);
    const int a_koff = (lane >> 4) << 3;
    const int b_m = lane >> 3;
    const int b_row = ((b_m >> 1) << 3) + (lane & 7);
    const int b_koff = (b_m & 1) << 3;

    for (int c = 0; c < nchunks; c++) {
        if (c + 1 < nchunks) asm volatile("cp.async.wait_group 1;" ::: "memory");
        else                 asm volatile("cp.async.wait_group 0;" ::: "memory");
        __syncthreads();

        const uint32_t a_u = as_u + (uint32_t)(c & 1) * A_STAGE_BYTES;
        const uint32_t b_u = bs_u + (uint32_t)(c & 1) * B_STAGE_BYTES;

        #pragma unroll
        for (int kk = 0; kk < 4; kk++) {
            const int kb = kk * 16;
            uint32_t afr[2][4], bfr[2][4];
            #pragma unroll
            for (int mi = 0; mi < 2; mi++) {
                const uint32_t addr = a_u +
                    (((wm + mi * 16 + a_row) * TS + kb + a_koff) << 1);
                ldmatrix_x4(afr[mi], addr);
            }
            #pragma unroll
            for (int nip = 0; nip < 2; nip++) {
                const uint32_t addr = b_u +
                    (((wn + nip * 16 + b_row) * TS + kb + b_koff) << 1);
                ldmatrix_x4(bfr[nip], addr);
            }
            #pragma unroll
            for (int mi = 0; mi < 2; mi++)
                #pragma unroll
                for (int nip = 0; nip < 2; nip++) {
                    mma_bf16(acc[mi][2 * nip],     afr[mi], &bfr[nip][0]);
                    mma_bf16(acc[mi][2 * nip + 1], afr[mi], &bfr[nip][2]);
                }
        }
        __syncthreads();
        if (c + 2 < nchunks) {
            ISSUE_STAGE(c & 1);
        }
    }
#undef ISSUE_STAGE

    const int g = lane >> 2;
    const int tig = lane & 3;
    #pragma unroll
    for (int mi = 0; mi < 2; mi++) {
        const int r0 = bm + wm + mi * 16 + g;
        const int r1 = r0 + 8;
        #pragma unroll
        for (int ni = 0; ni < 4; ni++) {
            const int col = bn + wn + ni * 8 + tig * 2;
            const float b0 = bias[col], b1 = bias[col + 1];
            float v0 = acc[mi][ni][0] + b0;
            float v1 = acc[mi][ni][1] + b1;
            float v2 = acc[mi][ni][2] + b0;
            float v3 = acc[mi][ni][3] + b1;
            if (mode & 1) {
                if (mode == 1) {
                    v0 = fmaxf(v0, 0.f); v1 = fmaxf(v1, 0.f);
                    v2 = fmaxf(v2, 0.f); v3 = fmaxf(v3, 0.f);
                }
                *(__nv_bfloat162*)(Cb + (size_t)r0 * N + col) =
                    __nv_bfloat162(__float2bfloat16(v0), __float2bfloat16(v1));
                *(__nv_bfloat162*)(Cb + (size_t)r1 * N + col) =
                    __nv_bfloat162(__float2bfloat16(v2), __float2bfloat16(v3));
            } else {
                if (mode == 2) {
                    float2 s0 = *reinterpret_cast<const float2*>(Res + (size_t)r0 * N + col);
                    float2 s1 = *reinterpret_cast<const float2*>(Res + (size_t)r1 * N + col);
                    v0 += s0.x; v1 += s0.y; v2 += s1.x; v3 += s1.y;
                }
                *reinterpret_cast<float2*>(C + (size_t)r0 * N + col) = make_float2(v0, v1);
                *reinterpret_cast<float2*>(C + (size_t)r1 * N + col) = make_float2(v2, v3);
            }
        }
    }
}

// ---------------- one merged packing kernel (incl. positional encoding) ----------------
// ranges: wc 180224 | wqkv 917504 | mapT 262144 | finalT 262144 | ffn1T 524288 |
//         ffn2T 524288 | pe 6400   total 2676992 = 10457*256
__global__ void pack_all_kernel(
    const float* __restrict__ conv_w,
    const float* __restrict__ q_w, const float* __restrict__ k_w,
    const float* __restrict__ v_w, const float* __restrict__ qv_w,
    const float* __restrict__ q_b, const float* __restrict__ k_b,
    const float* __restrict__ v_b, const float* __restrict__ qv_b,
    const float* __restrict__ map_w, const float* __restrict__ final_w,
    const float* __restrict__ ffn1_w, const float* __restrict__ ffn2_w)
{
    int idx = blockIdx.x * 256 + threadIdx.x;
    if (idx < 180224) {
        int n = idx / CONVKP, k = idx % CONVKP;
        g_wc[idx] = (k < CONVK) ? __float2bfloat16(conv_w[(size_t)n * CONVK + k])
                                : __float2bfloat16(0.f);
        return;
    }
    idx -= 180224;
    if (idx < 917504) {
        int n = idx / DMODEL, k = idx % DMODEL;
        float w;
        if (n < 512)       w = q_w[(size_t)k * 512 + n];
        else if (n < 1024) w = k_w[(size_t)k * 512 + (n - 512)];
        else if (n < 1536) w = v_w[(size_t)k * 512 + (n - 1024)];
        else               w = qv_w[(size_t)k * 256 + (n - 1536)];
        g_wqkv[idx] = __float2bfloat16(w);
        if (k == 0) {
            float b;
            if (n < 512)       b = q_b[n];
            else if (n < 1024) b = k_b[n - 512];
            else if (n < 1536) b = v_b[n - 1024];
            else               b = qv_b[n - 1536];
            g_bqkv[n] = b;
        }
        return;
    }
    idx -= 917504;
    if (idx < 262144) {
        int n = idx / 512, k = idx % 512;
        g_mapT[idx] = __float2bfloat16(map_w[(size_t)k * 512 + n]);
        return;
    }
    idx -= 262144;
    if (idx < 262144) {
        int n = idx / 512, k = idx % 512;
        g_finalT[idx] = __float2bfloat16(final_w[(size_t)k * 512 + n]);
        return;
    }
    idx -= 262144;
    if (idx < 524288) {
        int n = idx / 512, k = idx % 512;
        g_ffn1T[idx] = __float2bfloat16(ffn1_w[(size_t)k * 1024 + n]);
        return;
    }
    idx -= 524288;
    if (idx < 524288) {
        int n = idx / 1024, k = idx % 1024;
        g_ffn2T[idx] = __float2bfloat16(ffn2_w[(size_t)k * 512 + n]);
        return;
    }
    idx -= 524288;
    if (idx < 6400) {                    // positional encoding (float64 formula)
        const int pos = idx / HEMB;
        const int d = idx % HEMB;
        const int j = d >> 1;
        const double n = 1.0 / (1.0 + exp(-1.0));
        double val;
        if ((d & 1) == 0)
            val = sin((double)pos * pow(10000.0, -(double)j / 64.0));
        else
            val = cos((double)pos * pow(10000.0, -(double)(2 * j + 1) / 128.0));
        g_pe[pos * HEMB + d] = (float)(n * val);
    }
}

// ---------------- im2col ----------------
__global__ void im2col_kernel(const float* __restrict__ img) {
    const int row = blockIdx.x;
    const int b = row / NPATCH;
    const int patch = row % NPATCH;
    const int ph = patch / 5, pw = patch % 5;
    for (int t = threadIdx.x; t < CONVKP; t += 256) {
        float val = 0.0f;
        if (t < CONVK) {
            int c = t / 225;
            int rem = t % 225;
            int ky = rem / 15, kx = rem % 15;
            val = img[(((size_t)b * 3 + c) * 75 + ph * 15 + ky) * 75 + pw * 15 + kx];
        }
        g_im2col[(size_t)row * CONVKP + t] = __float2bfloat16(val);
    }
}

// ---------------- assemble x_in[6656,512] (bf16), que folded in ----------------
__global__ void assemble_kernel(const float* __restrict__ cls_token,
                                const float* __restrict__ qst,
                                const float* __restrict__ qrep_w,
                                const float* __restrict__ qrep_b) {
    const int idx = blockIdx.x * 256 + threadIdx.x;
    const int row = idx >> 9;
    const int col = idx & 511;
    const int b = row / SEQ;
    const int s = row % SEQ;
    float val;
    if (col < HEMB) {
        if (s == 0) val = cls_token[col];
        else val = g_pemb[((size_t)b * NPATCH + s - 1) * HEMB + col] + g_pe[(s - 1) * HEMB + col];
    } else {
        const int c2 = col - HEMB;
        float acc = qrep_b[c2];
        #pragma unroll
        for (int j = 0; j < 18; j++)
            acc = fmaf(qst[b * 18 + j], qrep_w[j * HEMB + c2], acc);
        val = acc;
    }
    g_xin[idx] = __float2bfloat16(val);
}

// ---------------- LayerNorm: fp32 in, bf16 out ----------------
__global__ void __launch_bounds__(256) ln_kernel(const float* __restrict__ g,
                                                 const float* __restrict__ bta) {
    const int warp = threadIdx.x >> 5;
    const int lane = threadIdx.x & 31;
    const int row = blockIdx.x * 8 + warp;
    const float* xr = g_x + (size_t)row * DMODEL;
    float vals[16];
    float s = 0.f;
    #pragma unroll
    for (int w = 0; w < 4; w++) {
        float4 t = *reinterpret_cast<const float4*>(xr + w * 128 + lane * 4);
        vals[w * 4 + 0] = t.x; vals[w * 4 + 1] = t.y;
        vals[w * 4 + 2] = t.z; vals[w * 4 + 3] = t.w;
        s += t.x + t.y + t.z + t.w;
    }
    #pragma unroll
    for (int o = 16; o > 0; o >>= 1) s += __shfl_xor_sync(0xffffffffu, s, o);
    const float mean = s * (1.0f / DMODEL);
    float sq = 0.f;
    #pragma unroll
    for (int i = 0; i < 16; i++) { float d = vals[i] - mean; sq += d * d; }
    #pragma unroll
    for (int o = 16; o > 0; o >>= 1) sq += __shfl_xor_sync(0xffffffffu, sq, o);
    const float rstd = rsqrtf(sq * (1.0f / DMODEL) + 1e-5f);
    bf16* hr = g_h + (size_t)row * DMODEL;
    #pragma unroll
    for (int w = 0; w < 4; w++) {
        float o0 = (vals[w * 4 + 0] - mean) * rstd * g[w * 128 + lane * 4 + 0] + bta[w * 128 + lane * 4 + 0];
        float o1 = (vals[w * 4 + 1] - mean) * rstd * g[w * 128 + lane * 4 + 1] + bta[w * 128 + lane * 4 + 1];
        float o2 = (vals[w * 4 + 2] - mean) * rstd * g[w * 128 + lane * 4 + 2] + bta[w * 128 + lane * 4 + 2];
        float o3 = (vals[w * 4 + 3] - mean) * rstd * g[w * 128 + lane * 4 + 3] + bta[w * 128 + lane * 4 + 3];
        *(__nv_bfloat162*)(hr + w * 128 + lane * 4)     = __nv_bfloat162(__float2bfloat16(o0), __float2bfloat16(o1));
        *(__nv_bfloat162*)(hr + w * 128 + lane * 4 + 2) = __nv_bfloat162(__float2bfloat16(o2), __float2bfloat16(o3));
    }
}

// ---------------- compositional attention: 4 CTAs per batch (2 heads each) ----------------
// reads bf16 g_qkvb (stride 1792): q=0, k=512, v=1024, qv=1536; writes o bf16
// smem floats: vsb(u32 6656) wT(5824) qs(1716) ks(1716) s(728) vw(208) comp(208) qvd(32) sw(97)
#define ATTN_SMEM_FLOATS (6656 + 5824 + 1716 + 1716 + 728 + 208 + 208 + 32 + 97)
__global__ void __launch_bounds__(256) attn_kernel(const float* __restrict__ score_w,
                                                   const float* __restrict__ score_b) {
    extern __shared__ float sm[];
    uint32_t* vsb = (uint32_t*)sm;       // 26*256 u32: v bf16x2, [k*512 + r*64 + d]
    float* wT   = sm + 6656;             // [j=208][q pad 28]
    float* qs   = wT + 5824;             // [26][66]  (8B-aligned rows for f32x2)
    float* ks   = qs + 1716;
    float* s    = ks + 1716;             // [26][28]
    float* vw   = s + 728;               // [208]
    float* comp = vw + 208;              // [26][8]
    float* qvd  = comp + 208;            // [26]
    float* sw   = qvd + 32;              // [97]
    float* scratch = qs;                 // 16*112 = 1792 <= 3432 (qs+ks)

    const int b = blockIdx.x >> 2;
    const int h0 = (blockIdx.x & 3) * 2;
    const int tid = threadIdx.x;

    if (tid < 96) sw[tid] = score_w[tid];
    if (tid == 96) sw[96] = score_b[0];

    // V: direct bf16x2 copies from qkvb
    for (int i = tid; i < 26 * 256; i += 256) {
        const int row = i >> 8, cp = (i & 255) << 1;
        vsb[i] = *reinterpret_cast<const uint32_t*>(
            g_qkvb + ((size_t)b * 26 + row) * NQKV + 1024 + cp);
    }
    __syncthreads();

    // vw[k*8+r] = sum_d v[k,r,d] * sw[32+d]  (skewed)
    for (int i = tid; i < 208; i += 256) {
        float acc = 0.f;
        #pragma unroll 8
        for (int dpp = 0; dpp < 32; dpp++) {
            const int dp = (dpp + i) & 31;
            const float2 v = bf2_to_f2(vsb[i * 32 + dp]);
            acc += v.x * sw[32 + dp * 2] + v.y * sw[32 + dp * 2 + 1];
        }
        vw[i] = acc;
    }
    __syncthreads();

    for (int hh = 0; hh < 2; hh++) {
        const int h = h0 + hh;
        // load q,k bf16 -> fp32 smem (stride 66, rows 8B-aligned)
        for (int i = tid; i < 26 * 32; i += 256) {
            const int qi = i >> 5, dp = (i & 31) << 1;
            const float2 qv = bf2_to_f2(*reinterpret_cast<const uint32_t*>(
                g_qkvb + ((size_t)b * 26 + qi) * NQKV + h * 64 + dp));
            const float2 kv = bf2_to_f2(*reinterpret_cast<const uint32_t*>(
                g_qkvb + ((size_t)b * 26 + qi) * NQKV + 512 + h * 64 + dp));
            qs[qi * 66 + dp] = qv.x; qs[qi * 66 + dp + 1] = qv.y;
            ks[qi * 66 + dp] = kv.x; ks[qi * 66 + dp + 1] = kv.y;
        }
        __syncthreads();

        // scores: 2-ki blocking, packed f32x2 over d-pairs
        for (int i = tid; i < 338; i += 256) {
            const int qi = i / 13;
            const int k0 = (i % 13) * 2;
            u64t acc0 = 0ull, acc1 = 0ull;
            const float* qr = qs + qi * 66;
            const float* k0r = ks + k0 * 66;
            const float* k1r = k0r + 66;
            #pragma unroll 8
            for (int dp = 0; dp < 32; dp++) {
                const u64t qp  = *reinterpret_cast<const u64t*>(qr + 2 * dp);
                const u64t kp0 = *reinterpret_cast<const u64t*>(k0r + 2 * dp);
                const u64t kp1 = *reinterpret_cast<const u64t*>(k1r + 2 * dp);
                fma_x2(acc0, qp, kp0);
                fma_x2(acc1, qp, kp1);
            }
            const float2 a0 = unpack_ff(acc0);
            const float2 a1 = unpack_ff(acc1);
            s[qi * 28 + k0]     = (a0.x + a0.y) * 0.125f;
            s[qi * 28 + k0 + 1] = (a1.x + a1.y) * 0.125f;
        }
        if (tid < 26) {
            float acc = sw[96];
            #pragma unroll
            for (int j = 0; j < 32; j++)
                acc += __bfloat162float(g_qkvb[((size_t)b * 26 + tid) * NQKV + 1536 + h * 32 + j]) * sw[j];
            qvd[tid] = acc;
        }
        __syncthreads();

        // softmax over k
        if (tid < 26) {
            float mx = -1e30f;
            for (int k = 0; k < 26; k++) mx = fmaxf(mx, s[tid * 28 + k]);
            float sum = 0.f;
            for (int k = 0; k < 26; k++) {
                float e = expf(s[tid * 28 + k] - mx);
                s[tid * 28 + k] = e; sum += e;
            }
            float inv = 1.f / sum;
            for (int k = 0; k < 26; k++) s[tid * 28 + k] *= inv;
        }
        __syncthreads();

        // comp logits
        if (tid < 208) {
            const int qi = tid >> 3, r = tid & 7;
            float acc = qvd[qi];
            #pragma unroll
            for (int k = 0; k < 26; k++) acc += s[qi * 28 + k] * vw[k * 8 + r];
            comp[tid] = acc;
        }
        __syncthreads();

        // softmax over r
        if (tid < 26) {
            float mx = -1e30f;
            for (int r = 0; r < 8; r++) mx = fmaxf(mx, comp[tid * 8 + r]);
            float sum = 0.f;
            for (int r = 0; r < 8; r++) {
                float e = expf(comp[tid * 8 + r] - mx);
                comp[tid * 8 + r] = e; sum += e;
            }
            float inv = 1.f / sum;
            for (int r = 0; r < 8; r++) comp[tid * 8 + r] *= inv;
        }
        __syncthreads();

        // wT[j][q] = s[q][j>>3] * comp[q][j&7]
        for (int i = tid; i < 208 * 28; i += 256) {
            const int j = i / 28, q = i % 28;
            wT[i] = (q < 26) ? s[q * 28 + (j >> 3)] * comp[q * 8 + (j & 7)] : 0.f;
        }
        __syncthreads();

        // output phase 1: 224 threads = 7 qg x 16 dq x 2 j-halves; 104 j each, f32x2 FMA
        u64t oac[4][2];
        #pragma unroll
        for (int a = 0; a < 4; a++) { oac[a][0] = 0ull; oac[a][1] = 0ull; }
        const int qg = tid >> 5;
        const int dq = ((tid >> 1) & 15) << 2;
        const int jh = tid & 1;
        if (tid < 224) {
            const int q0 = qg * 4;
            const int j0 = jh * 104;
            #pragma unroll 4
            for (int jj = 0; jj < 104; jj++) {
                const int j = j0 + jj;
                const float4 w4 = *reinterpret_cast<const float4*>(wT + j * 28 + q0);
                const u64t v01 = bf2_to_fx2(vsb[j * 32 + (dq >> 1)]);
                const u64t v23 = bf2_to_fx2(vsb[j * 32 + (dq >> 1) + 1]);
                const u64t w0 = pack_ff(w4.x, w4.x);
                const u64t w1 = pack_ff(w4.y, w4.y);
                const u64t w2 = pack_ff(w4.z, w4.z);
                const u64t w3 = pack_ff(w4.w, w4.w);
                fma_x2(oac[0][0], w0, v01); fma_x2(oac[0][1], w0, v23);
                fma_x2(oac[1][0], w1, v01); fma_x2(oac[1][1], w1, v23);
                fma_x2(oac[2][0], w2, v01); fma_x2(oac[2][1], w2, v23);
                fma_x2(oac[3][0], w3, v01); fma_x2(oac[3][1], w3, v23);
            }
        }
        float oacc[4][4];
        #pragma unroll
        for (int a = 0; a < 4; a++) {
            const float2 p01 = unpack_ff(oac[a][0]);
            const float2 p23 = unpack_ff(oac[a][1]);
            oacc[a][0] = p01.x; oacc[a][1] = p01.y;
            oacc[a][2] = p23.x; oacc[a][3] = p23.y;
        }
        if (tid < 224 && jh == 1) {
            const int idx = qg * 16 + (dq >> 2);
            #pragma unroll
            for (int a = 0; a < 4; a++)
                #pragma unroll
                for (int d2 = 0; d2 < 4; d2++)
                    scratch[(a * 4 + d2) * 112 + idx] = oacc[a][d2];
        }
        __syncthreads();

        // output phase 2: jh==0 threads combine + store
        if (tid < 224 && jh == 0) {
            const int idx = qg * 16 + (dq >> 2);
            const int q0 = qg * 4;
            #pragma unroll
            for (int a = 0; a < 4; a++) {
                const int q = q0 + a;
                if (q < 26) {
                    float r0 = oacc[a][0] + scratch[(a * 4 + 0) * 112 + idx];
                    float r1 = oacc[a][1] + scratch[(a * 4 + 1) * 112 + idx];
                    float r2 = oacc[a][2] + scratch[(a * 4 + 2) * 112 + idx];
                    float r3 = oacc[a][3] + scratch[(a * 4 + 3) * 112 + idx];
                    bf16* dst = g_o + ((size_t)b * 26 + q) * 512 + h * 64 + dq;
                    *(__nv_bfloat162*)(dst) =
                        __nv_bfloat162(__float2bfloat16(r0), __float2bfloat16(r1));
                    *(__nv_bfloat162*)(dst + 2) =
                        __nv_bfloat162(__float2bfloat16(r2), __float2bfloat16(r3));
                }
            }
        }
        __syncthreads();
    }
}

// ---------------- classifier + log_softmax ----------------
__global__ void __launch_bounds__(256) cls_kernel(const float* __restrict__ out_w,
                                                  const float* __restrict__ out_b,
                                                  float* __restrict__ out) {
    const int warp = threadIdx.x >> 5;
    const int lane = threadIdx.x & 31;
    const int b = blockIdx.x * 8 + warp;
    const float* xr = g_x + (size_t)b * SEQ * DMODEL;
    float acc[10] = {};
    for (int d = lane; d < DMODEL; d += 32) {
        float xv = xr[d];
        #pragma unroll
        for (int c = 0; c < 10; c++) acc[c] = fmaf(xv, out_w[d * 10 + c], acc[c]);
    }
    #pragma unroll
    for (int c = 0; c < 10; c++)
        #pragma unroll
        for (int o = 16; o > 0; o >>= 1)
            acc[c] += __shfl_xor_sync(0xffffffffu, acc[c], o);
    if (lane == 0) {
        float y[10], mx = -1e30f;
        #pragma unroll
        for (int c = 0; c < 10; c++) { y[c] = acc[c] + out_b[c]; mx = fmaxf(mx, y[c]); }
        float sum = 0.f;
        #pragma unroll
        for (int c = 0; c < 10; c++) sum += expf(y[c] - mx);
        float lse = logf(sum) + mx;
        #pragma unroll
        for (int c = 0; c < 10; c++) out[b * 10 + c] = y[c] - lse;
    }
}

// ---------------- host orchestration ----------------
extern "C" void kernel_launch(void* const* d_in, const int* in_sizes, int n_in,
                              void* d_out, int out_size) {
    const float* img      = (const float*)d_in[0];
    const float* qst      = (const float*)d_in[1];
    const float* conv_w   = (const float*)d_in[2];
    const float* conv_b   = (const float*)d_in[3];
    const float* qrep_w   = (const float*)d_in[4];
    const float* qrep_b   = (const float*)d_in[5];
    const float* cls_tok  = (const float*)d_in[6];
    const float* map_w    = (const float*)d_in[7];
    const float* map_b    = (const float*)d_in[8];
    const float* norm1_g  = (const float*)d_in[9];
    const float* norm1_b  = (const float*)d_in[10];
    const float* norm2_g  = (const float*)d_in[11];
    const float* norm2_b  = (const float*)d_in[12];
    const float* q_w      = (const float*)d_in[13];
    const float* q_b      = (const float*)d_in[14];
    const float* k_w      = (const float*)d_in[15];
    const float* k_b      = (const float*)d_in[16];
    const float* v_w      = (const float*)d_in[17];
    const float* v_b      = (const float*)d_in[18];
    const float* qv_w     = (const float*)d_in[19];
    const float* qv_b     = (const float*)d_in[20];
    const float* score_w  = (const float*)d_in[21];
    const float* score_b  = (const float*)d_in[22];
    const float* final_w  = (const float*)d_in[23];
    const float* final_b  = (const float*)d_in[24];
    const float* ffn1_w   = (const float*)d_in[25];
    const float* ffn1_b   = (const float*)d_in[26];
    const float* ffn2_w   = (const float*)d_in[27];
    const float* ffn2_b   = (const float*)d_in[28];
    const float* out_w    = (const float*)d_in[29];
    const float* out_b    = (const float*)d_in[30];

    bf16 *p_im2col, *p_wc, *p_mapT, *p_wqkv, *p_finalT,
         *p_ffn1T, *p_ffn2T, *p_xin, *p_h, *p_qkvb, *p_o, *p_t;
    float *p_bqkv, *p_pemb, *p_x;
    cudaGetSymbolAddress((void**)&p_im2col, g_im2col);
    cudaGetSymbolAddress((void**)&p_wc,     g_wc);
    cudaGetSymbolAddress((void**)&p_mapT,   g_mapT);
    cudaGetSymbolAddress((void**)&p_wqkv,   g_wqkv);
    cudaGetSymbolAddress((void**)&p_finalT, g_finalT);
    cudaGetSymbolAddress((void**)&p_ffn1T,  g_ffn1T);
    cudaGetSymbolAddress((void**)&p_ffn2T,  g_ffn2T);
    cudaGetSymbolAddress((void**)&p_xin,    g_xin);
    cudaGetSymbolAddress((void**)&p_h,      g_h);
    cudaGetSymbolAddress((void**)&p_qkvb,   g_qkvb);
    cudaGetSymbolAddress((void**)&p_o,      g_o);
    cudaGetSymbolAddress((void**)&p_t,      g_t);
    cudaGetSymbolAddress((void**)&p_bqkv,   g_bqkv);
    cudaGetSymbolAddress((void**)&p_pemb,   g_pemb);
    cudaGetSymbolAddress((void**)&p_x,      g_x);

    cudaFuncSetAttribute(gemm_tc, cudaFuncAttributeMaxDynamicSharedMemorySize, GEMM_SMEM_BYTES);
    cudaFuncSetAttribute(attn_kernel, cudaFuncAttributeMaxDynamicSharedMemorySize,
                         ATTN_SMEM_FLOATS * (int)sizeof(float));

    // ---- packing / front end ----
    pack_all_kernel<<<10457, 256>>>(conv_w, q_w, k_w, v_w, qv_w, q_b, k_b, v_b, qv_b,
                                    map_w, final_w, ffn1_w, ffn2_w);
    im2col_kernel<<<BATCH * NPATCH, 256>>>(img);

    // conv: [6400,704] x [256,704]^T
    gemm_tc<<<dim3(2, 100), 256, GEMM_SMEM_BYTES>>>(
        p_im2col, p_wc, conv_b, nullptr, p_pemb, nullptr, 6400, HEMB, CONVKP, 0);
    assemble_kernel<<<NROWS * DMODEL / 256, 256>>>(cls_tok, qst, qrep_w, qrep_b);
    // map: [6656,512] x [512,512]^T
    gemm_tc<<<dim3(4, 104), 256, GEMM_SMEM_BYTES>>>(
        p_xin, p_mapT, map_b, nullptr, p_x, nullptr, NROWS, DMODEL, DMODEL, 0);

    // ---- 4 transformer iterations ----
    for (int it = 0; it < 4; it++) {
        ln_kernel<<<NROWS / 8, 256>>>(norm1_g, norm1_b);
        gemm_tc<<<dim3(14, 104), 256, GEMM_SMEM_BYTES>>>(
            p_h, p_wqkv, p_bqkv, nullptr, nullptr, p_qkvb, NROWS, NQKV, DMODEL, 3);
        attn_kernel<<<4 * BATCH, 256, ATTN_SMEM_FLOATS * (int)sizeof(float)>>>(score_w, score_b);
        gemm_tc<<<dim3(4, 104), 256, GEMM_SMEM_BYTES>>>(
            p_o, p_finalT, final_b, p_x, p_x, nullptr, NROWS, DMODEL, DMODEL, 2);
        ln_kernel<<<NROWS / 8, 256>>>(norm2_g, norm2_b);
        gemm_tc<<<dim3(8, 104), 256, GEMM_SMEM_BYTES>>>(
            p_h, p_ffn1T, ffn1_b, nullptr, nullptr, p_t, NROWS, 2 * DMODEL, DMODEL, 1);
        gemm_tc<<<dim3(4, 104), 256, GEMM_SMEM_BYTES>>>(
            p_t, p_ffn2T, ffn2_b, p_x, p_x, nullptr, NROWS, DMODEL, 2 * DMODEL, 2);
    }

    // ---- classifier ----
    cls_kernel<<<BATCH / 8, 256>>>(out_w, out_b, (float*)d_out);
}

// round 14
// speedup vs baseline: 1.0289x; 1.0289x over previous
#include <cuda_runtime.h>
#include <cuda_bf16.h>
#include <math.h>
#include <stdint.h>

// ---------------- constants ----------------
#define BATCH   256
#define SEQ     26
#define DMODEL  512
#define HEMB    256
#define NHEADS  8
#define NROWS   (BATCH*SEQ)     // 6656
#define NPATCH  25
#define CONVK   675             // 3*15*15
#define CONVKP  704             // padded to multiple of 64
#define NQKV    1792            // 512+512+512+256 fused projection width

typedef __nv_bfloat16 bf16;

// ---------------- scratch (device globals; no runtime allocation) ----------------
__device__ bf16  g_im2col[BATCH*NPATCH*CONVKP];
__device__ bf16  g_wc[HEMB*CONVKP];          // [N=256][K=704]
__device__ bf16  g_mapT[DMODEL*DMODEL];      // [N=512][K=512]
__device__ bf16  g_wqkv[NQKV*DMODEL];        // [N=1792][K=512]
__device__ bf16  g_finalT[DMODEL*DMODEL];
__device__ bf16  g_ffn1T[2*DMODEL*DMODEL];   // [N=1024][K=512]
__device__ bf16  g_ffn2T[DMODEL*2*DMODEL];   // [N=512][K=1024]
__device__ float g_bqkv[NQKV];
__device__ float g_pe[NPATCH*HEMB];
__device__ float g_pemb[BATCH*NPATCH*HEMB];
__device__ bf16  g_xin[NROWS*DMODEL];
__device__ float g_x[NROWS*DMODEL];
__device__ bf16  g_h[NROWS*DMODEL];
__device__ bf16  g_qkvb[NROWS*NQKV];         // bf16 qkv output
__device__ bf16  g_o[NROWS*DMODEL];
__device__ bf16  g_t[NROWS*2*DMODEL];

// ---------------- helpers ----------------
__device__ __forceinline__ uint32_t smem_u32(const void* p) {
    uint32_t a;
    asm("{ .reg .u64 t; cvta.to.shared.u64 t, %1; cvt.u32.u64 %0, t; }" : "=r"(a) : "l"(p));
    return a;
}
__device__ __forceinline__ void mma_bf16(float* d, const uint32_t* a, const uint32_t* b) {
    asm volatile(
        "mma.sync.aligned.m16n8k16.row.col.f32.bf16.bf16.f32 "
        "{%0,%1,%2,%3}, {%4,%5,%6,%7}, {%8,%9}, {%0,%1,%2,%3};"
        : "+f"(d[0]), "+f"(d[1]), "+f"(d[2]), "+f"(d[3])
        : "r"(a[0]), "r"(a[1]), "r"(a[2]), "r"(a[3]), "r"(b[0]), "r"(b[1]));
}
__device__ __forceinline__ void ldmatrix_x4(uint32_t* r, uint32_t addr) {
    asm volatile("ldmatrix.sync.aligned.m8n8.x4.shared.b16 {%0,%1,%2,%3}, [%4];"
                 : "=r"(r[0]), "=r"(r[1]), "=r"(r[2]), "=r"(r[3]) : "r"(addr));
}
__device__ __forceinline__ void cp_async16(uint32_t dst, const void* src) {
    asm volatile("cp.async.cg.shared.global [%0], [%1], 16;" :: "r"(dst), "l"(src));
}
__device__ __forceinline__ float2 bf2_to_f2(uint32_t u) {
    __nv_bfloat162 h = *reinterpret_cast<__nv_bfloat162*>(&u);
    return __bfloat1622float2(h);
}
// packed f32x2 helpers (sm_103a FFMA2 path)
typedef unsigned long long u64t;
__device__ __forceinline__ u64t pack_ff(float lo, float hi) {
    u64t r;
    asm("mov.b64 %0, {%1, %2};" : "=l"(r) : "f"(lo), "f"(hi));
    return r;
}
__device__ __forceinline__ void fma_x2(u64t& d, u64t a, u64t b) {
    asm("fma.rn.f32x2 %0, %1, %2, %3;" : "=l"(d) : "l"(a), "l"(b), "l"(d));
}
__device__ __forceinline__ float2 unpack_ff(u64t v) {
    float lo, hi;
    asm("mov.b64 {%0, %1}, %2;" : "=f"(lo), "=f"(hi) : "l"(v));
    return make_float2(lo, hi);
}
__device__ __forceinline__ u64t bf2_to_fx2(uint32_t u) {
    uint32_t lo = u << 16;
    uint32_t hi = u & 0xffff0000u;
    u64t r;
    asm("mov.b64 %0, {%1, %2};" : "=l"(r) : "r"(lo), "r"(hi));
    return r;
}

// ---------------- bf16 mma.sync GEMM, 64x128 tile, 2-stage cp.async, 3 CTAs/SM ----------------
// C[M,N] = epi(A[M,K]bf16 @ B[N,K]bf16^T + bias[N])
// mode 0: bias -> fp32 C   mode 1: bias+relu -> bf16 Cb
// mode 2: bias+Res -> fp32 C   mode 3: bias -> bf16 Cb
#define BM 64
#define BN 128
#define BK 64
#define TS 72
#define A_STAGE_BYTES (64 * TS * 2)      // 9216
#define B_STAGE_BYTES (128 * TS * 2)     // 18432
#define GEMM_SMEM_BYTES (2 * (A_STAGE_BYTES + B_STAGE_BYTES))   // 55296

__global__ void __launch_bounds__(256, 3) gemm_tc(
    const bf16* __restrict__ A, const bf16* __restrict__ B,
    const float* __restrict__ bias, const float* __restrict__ Res,
    float* __restrict__ C, bf16* __restrict__ Cb,
    int M, int N, int K, int mode)
{
    extern __shared__ bf16 smem[];
    const uint32_t as_u = smem_u32(smem);
    const uint32_t bs_u = as_u + 2 * A_STAGE_BYTES;

    const int bm = blockIdx.y * BM;
    const int bn = blockIdx.x * BN;
    const int tid = threadIdx.x;
    const int lane = tid & 31;
    const int wid = tid >> 5;
    const int wm = (wid & 1) * 32;
    const int wn = (wid >> 1) * 32;

    const int rbase = tid >> 3;
    const int kq = (tid & 7) << 3;
    const uint32_t sO = (uint32_t)(rbase * TS + kq) * 2;

    const bf16* pA = A + (size_t)(bm + rbase) * K + kq;
    const bf16* pB = B + (size_t)(bn + rbase) * K + kq;
    const size_t rowstep = (size_t)32 * K;

    float acc[2][4][4];
    #pragma unroll
    for (int mi = 0; mi < 2; mi++)
        #pragma unroll
        for (int ni = 0; ni < 4; ni++)
            #pragma unroll
            for (int r = 0; r < 4; r++) acc[mi][ni][r] = 0.0f;

    const int nchunks = K / BK;

#define ISSUE_STAGE(s)                                                   \
    do {                                                                 \
        const uint32_t ab = as_u + (uint32_t)(s) * A_STAGE_BYTES + sO;   \
        const uint32_t bb = bs_u + (uint32_t)(s) * B_STAGE_BYTES + sO;   \
        cp_async16(ab,         pA);                                      \
        cp_async16(ab + 4608,  pA + rowstep);                            \
        cp_async16(bb,         pB);                                      \
        cp_async16(bb + 4608,  pB + rowstep);                            \
        cp_async16(bb + 9216,  pB + 2 * rowstep);                        \
        cp_async16(bb + 13824, pB + 3 * rowstep);                        \
        asm volatile("cp.async.commit_group;" ::: "memory");             \
        pA += BK; pB += BK;                                              \
    } while (0)

    ISSUE_STAGE(0);
    if (nchunks > 1) ISSUE_STAGE(1);

    const int a_row = (lane & 15);
    const int a_koff = (lane >> 4) << 3;
    const int b_m = lane >> 3;
    const int b_row = ((b_m >> 1) << 3) + (lane & 7);
    const int b_koff = (b_m & 1) << 3;

    for (int c = 0; c < nchunks; c++) {
        if (c + 1 < nchunks) asm volatile("cp.async.wait_group 1;" ::: "memory");
        else                 asm volatile("cp.async.wait_group 0;" ::: "memory");
        __syncthreads();

        const uint32_t a_u = as_u + (uint32_t)(c & 1) * A_STAGE_BYTES;
        const uint32_t b_u = bs_u + (uint32_t)(c & 1) * B_STAGE_BYTES;

        #pragma unroll
        for (int kk = 0; kk < 4; kk++) {
            const int kb = kk * 16;
            uint32_t afr[2][4], bfr[2][4];
            #pragma unroll
            for (int mi = 0; mi < 2; mi++) {
                const uint32_t addr = a_u +
                    (((wm + mi * 16 + a_row) * TS + kb + a_koff) << 1);
                ldmatrix_x4(afr[mi], addr);
            }
            #pragma unroll
            for (int nip = 0; nip < 2; nip++) {
                const uint32_t addr = b_u +
                    (((wn + nip * 16 + b_row) * TS + kb + b_koff) << 1);
                ldmatrix_x4(bfr[nip], addr);
            }
            #pragma unroll
            for (int mi = 0; mi < 2; mi++)
                #pragma unroll
                for (int nip = 0; nip < 2; nip++) {
                    mma_bf16(acc[mi][2 * nip],     afr[mi], &bfr[nip][0]);
                    mma_bf16(acc[mi][2 * nip + 1], afr[mi], &bfr[nip][2]);
                }
        }
        __syncthreads();
        if (c + 2 < nchunks) {
            ISSUE_STAGE(c & 1);
        }
    }
#undef ISSUE_STAGE

    const int g = lane >> 2;
    const int tig = lane & 3;
    #pragma unroll
    for (int mi = 0; mi < 2; mi++) {
        const int r0 = bm + wm + mi * 16 + g;
        const int r1 = r0 + 8;
        #pragma unroll
        for (int ni = 0; ni < 4; ni++) {
            const int col = bn + wn + ni * 8 + tig * 2;
            const float b0 = bias[col], b1 = bias[col + 1];
            float v0 = acc[mi][ni][0] + b0;
            float v1 = acc[mi][ni][1] + b1;
            float v2 = acc[mi][ni][2] + b0;
            float v3 = acc[mi][ni][3] + b1;
            if (mode & 1) {
                if (mode == 1) {
                    v0 = fmaxf(v0, 0.f); v1 = fmaxf(v1, 0.f);
                    v2 = fmaxf(v2, 0.f); v3 = fmaxf(v3, 0.f);
                }
                *(__nv_bfloat162*)(Cb + (size_t)r0 * N + col) =
                    __nv_bfloat162(__float2bfloat16(v0), __float2bfloat16(v1));
                *(__nv_bfloat162*)(Cb + (size_t)r1 * N + col) =
                    __nv_bfloat162(__float2bfloat16(v2), __float2bfloat16(v3));
            } else {
                if (mode == 2) {
                    float2 s0 = *reinterpret_cast<const float2*>(Res + (size_t)r0 * N + col);
                    float2 s1 = *reinterpret_cast<const float2*>(Res + (size_t)r1 * N + col);
                    v0 += s0.x; v1 += s0.y; v2 += s1.x; v3 += s1.y;
                }
                *reinterpret_cast<float2*>(C + (size_t)r0 * N + col) = make_float2(v0, v1);
                *reinterpret_cast<float2*>(C + (size_t)r1 * N + col) = make_float2(v2, v3);
            }
        }
    }
}

// ---------------- one merged packing kernel (incl. positional encoding) ----------------
__global__ void pack_all_kernel(
    const float* __restrict__ conv_w,
    const float* __restrict__ q_w, const float* __restrict__ k_w,
    const float* __restrict__ v_w, const float* __restrict__ qv_w,
    const float* __restrict__ q_b, const float* __restrict__ k_b,
    const float* __restrict__ v_b, const float* __restrict__ qv_b,
    const float* __restrict__ map_w, const float* __restrict__ final_w,
    const float* __restrict__ ffn1_w, const float* __restrict__ ffn2_w)
{
    int idx = blockIdx.x * 256 + threadIdx.x;
    if (idx < 180224) {
        int n = idx / CONVKP, k = idx % CONVKP;
        g_wc[idx] = (k < CONVK) ? __float2bfloat16(conv_w[(size_t)n * CONVK + k])
                                : __float2bfloat16(0.f);
        return;
    }
    idx -= 180224;
    if (idx < 917504) {
        int n = idx / DMODEL, k = idx % DMODEL;
        float w;
        if (n < 512)       w = q_w[(size_t)k * 512 + n];
        else if (n < 1024) w = k_w[(size_t)k * 512 + (n - 512)];
        else if (n < 1536) w = v_w[(size_t)k * 512 + (n - 1024)];
        else               w = qv_w[(size_t)k * 256 + (n - 1536)];
        g_wqkv[idx] = __float2bfloat16(w);
        if (k == 0) {
            float b;
            if (n < 512)       b = q_b[n];
            else if (n < 1024) b = k_b[n - 512];
            else if (n < 1536) b = v_b[n - 1024];
            else               b = qv_b[n - 1536];
            g_bqkv[n] = b;
        }
        return;
    }
    idx -= 917504;
    if (idx < 262144) {
        int n = idx / 512, k = idx % 512;
        g_mapT[idx] = __float2bfloat16(map_w[(size_t)k * 512 + n]);
        return;
    }
    idx -= 262144;
    if (idx < 262144) {
        int n = idx / 512, k = idx % 512;
        g_finalT[idx] = __float2bfloat16(final_w[(size_t)k * 512 + n]);
        return;
    }
    idx -= 262144;
    if (idx < 524288) {
        int n = idx / 512, k = idx % 512;
        g_ffn1T[idx] = __float2bfloat16(ffn1_w[(size_t)k * 1024 + n]);
        return;
    }
    idx -= 524288;
    if (idx < 524288) {
        int n = idx / 1024, k = idx % 1024;
        g_ffn2T[idx] = __float2bfloat16(ffn2_w[(size_t)k * 512 + n]);
        return;
    }
    idx -= 524288;
    if (idx < 6400) {                    // positional encoding (float64 formula)
        const int pos = idx / HEMB;
        const int d = idx % HEMB;
        const int j = d >> 1;
        const double n = 1.0 / (1.0 + exp(-1.0));
        double val;
        if ((d & 1) == 0)
            val = sin((double)pos * pow(10000.0, -(double)j / 64.0));
        else
            val = cos((double)pos * pow(10000.0, -(double)(2 * j + 1) / 128.0));
        g_pe[pos * HEMB + d] = (float)(n * val);
    }
}

// ---------------- im2col ----------------
__global__ void im2col_kernel(const float* __restrict__ img) {
    const int row = blockIdx.x;
    const int b = row / NPATCH;
    const int patch = row % NPATCH;
    const int ph = patch / 5, pw = patch % 5;
    for (int t = threadIdx.x; t < CONVKP; t += 256) {
        float val = 0.0f;
        if (t < CONVK) {
            int c = t / 225;
            int rem = t % 225;
            int ky = rem / 15, kx = rem % 15;
            val = img[(((size_t)b * 3 + c) * 75 + ph * 15 + ky) * 75 + pw * 15 + kx];
        }
        g_im2col[(size_t)row * CONVKP + t] = __float2bfloat16(val);
    }
}

// ---------------- assemble x_in[6656,512] (bf16), que folded with smem qst ----------------
__global__ void assemble_kernel(const float* __restrict__ cls_token,
                                const float* __restrict__ qst,
                                const float* __restrict__ qrep_w,
                                const float* __restrict__ qrep_b) {
    __shared__ float qsh[18];
    const int tid = threadIdx.x;
    const int idx = blockIdx.x * 256 + tid;
    const int row = blockIdx.x >> 1;            // 512 cols = 2 blocks per row
    const int col = idx & 511;
    const int b = row / SEQ;
    const int s = row % SEQ;
    if (tid < 18) qsh[tid] = qst[b * 18 + tid];
    __syncthreads();
    float val;
    if (col < HEMB) {
        if (s == 0) val = cls_token[col];
        else val = g_pemb[((size_t)b * NPATCH + s - 1) * HEMB + col] + g_pe[(s - 1) * HEMB + col];
    } else {
        const int c2 = col - HEMB;
        float acc = qrep_b[c2];
        #pragma unroll
        for (int j = 0; j < 18; j++)
            acc = fmaf(qsh[j], qrep_w[j * HEMB + c2], acc);
        val = acc;
    }
    g_xin[idx] = __float2bfloat16(val);
}

// ---------------- LayerNorm: fp32 in, bf16 out ----------------
__global__ void __launch_bounds__(256) ln_kernel(const float* __restrict__ g,
                                                 const float* __restrict__ bta) {
    const int warp = threadIdx.x >> 5;
    const int lane = threadIdx.x & 31;
    const int row = blockIdx.x * 8 + warp;
    const float* xr = g_x + (size_t)row * DMODEL;
    float vals[16];
    float s = 0.f;
    #pragma unroll
    for (int w = 0; w < 4; w++) {
        float4 t = *reinterpret_cast<const float4*>(xr + w * 128 + lane * 4);
        vals[w * 4 + 0] = t.x; vals[w * 4 + 1] = t.y;
        vals[w * 4 + 2] = t.z; vals[w * 4 + 3] = t.w;
        s += t.x + t.y + t.z + t.w;
    }
    #pragma unroll
    for (int o = 16; o > 0; o >>= 1) s += __shfl_xor_sync(0xffffffffu, s, o);
    const float mean = s * (1.0f / DMODEL);
    float sq = 0.f;
    #pragma unroll
    for (int i = 0; i < 16; i++) { float d = vals[i] - mean; sq += d * d; }
    #pragma unroll
    for (int o = 16; o > 0; o >>= 1) sq += __shfl_xor_sync(0xffffffffu, sq, o);
    const float rstd = rsqrtf(sq * (1.0f / DMODEL) + 1e-5f);
    bf16* hr = g_h + (size_t)row * DMODEL;
    #pragma unroll
    for (int w = 0; w < 4; w++) {
        float o0 = (vals[w * 4 + 0] - mean) * rstd * g[w * 128 + lane * 4 + 0] + bta[w * 128 + lane * 4 + 0];
        float o1 = (vals[w * 4 + 1] - mean) * rstd * g[w * 128 + lane * 4 + 1] + bta[w * 128 + lane * 4 + 1];
        float o2 = (vals[w * 4 + 2] - mean) * rstd * g[w * 128 + lane * 4 + 2] + bta[w * 128 + lane * 4 + 2];
        float o3 = (vals[w * 4 + 3] - mean) * rstd * g[w * 128 + lane * 4 + 3] + bta[w * 128 + lane * 4 + 3];
        *(__nv_bfloat162*)(hr + w * 128 + lane * 4)     = __nv_bfloat162(__float2bfloat16(o0), __float2bfloat16(o1));
        *(__nv_bfloat162*)(hr + w * 128 + lane * 4 + 2) = __nv_bfloat162(__float2bfloat16(o2), __float2bfloat16(o3));
    }
}

// ---------------- compositional attention: 4 CTAs per batch (2 heads each) ----------------
// reads bf16 g_qkvb (stride 1792): q=0, k=512, v=1024, qv=1536; writes o bf16
// smem floats: vsb(u32 6656) wT(5824) qs(1716) ks(1716) s(728) vw(208) qvd(32) sw(97)
#define ATTN_SMEM_FLOATS (6656 + 5824 + 1716 + 1716 + 728 + 208 + 32 + 97)
__global__ void __launch_bounds__(256) attn_kernel(const float* __restrict__ score_w,
                                                   const float* __restrict__ score_b) {
    extern __shared__ float sm[];
    uint32_t* vsb = (uint32_t*)sm;       // 26*256 u32: v bf16x2, [k*512 + r*64 + d]
    float* wT   = sm + 6656;             // [j=208][q pad 28]
    float* qs   = wT + 5824;             // [26][66]  (8B-aligned rows for f32x2)
    float* ks   = qs + 1716;
    float* s    = ks + 1716;             // [26][28]
    float* vw   = s + 728;               // [208]
    float* qvd  = vw + 208;              // [26]
    float* sw   = qvd + 32;              // [97]
    float* scratch = qs;                 // 16*112 = 1792 <= 3432 (qs+ks)

    const int b = blockIdx.x >> 2;
    const int h0 = (blockIdx.x & 3) * 2;
    const int tid = threadIdx.x;

    if (tid < 96) sw[tid] = score_w[tid];
    if (tid == 96) sw[96] = score_b[0];

    // V: direct bf16x2 copies from qkvb
    for (int i = tid; i < 26 * 256; i += 256) {
        const int row = i >> 8, cp = (i & 255) << 1;
        vsb[i] = *reinterpret_cast<const uint32_t*>(
            g_qkvb + ((size_t)b * 26 + row) * NQKV + 1024 + cp);
    }
    __syncthreads();

    // vw[k*8+r] = sum_d v[k,r,d] * sw[32+d]  (skewed)
    for (int i = tid; i < 208; i += 256) {
        float acc = 0.f;
        #pragma unroll 8
        for (int dpp = 0; dpp < 32; dpp++) {
            const int dp = (dpp + i) & 31;
            const float2 v = bf2_to_f2(vsb[i * 32 + dp]);
            acc += v.x * sw[32 + dp * 2] + v.y * sw[32 + dp * 2 + 1];
        }
        vw[i] = acc;
    }
    __syncthreads();

    for (int hh = 0; hh < 2; hh++) {
        const int h = h0 + hh;
        // load q,k bf16 -> fp32 smem (stride 66, rows 8B-aligned)
        for (int i = tid; i < 26 * 32; i += 256) {
            const int qi = i >> 5, dp = (i & 31) << 1;
            const float2 qv = bf2_to_f2(*reinterpret_cast<const uint32_t*>(
                g_qkvb + ((size_t)b * 26 + qi) * NQKV + h * 64 + dp));
            const float2 kv = bf2_to_f2(*reinterpret_cast<const uint32_t*>(
                g_qkvb + ((size_t)b * 26 + qi) * NQKV + 512 + h * 64 + dp));
            qs[qi * 66 + dp] = qv.x; qs[qi * 66 + dp + 1] = qv.y;
            ks[qi * 66 + dp] = kv.x; ks[qi * 66 + dp + 1] = kv.y;
        }
        __syncthreads();

        // scores: 2-ki blocking, packed f32x2 over d-pairs
        for (int i = tid; i < 338; i += 256) {
            const int qi = i / 13;
            const int k0 = (i % 13) * 2;
            u64t acc0 = 0ull, acc1 = 0ull;
            const float* qr = qs + qi * 66;
            const float* k0r = ks + k0 * 66;
            const float* k1r = k0r + 66;
            #pragma unroll 8
            for (int dp = 0; dp < 32; dp++) {
                const u64t qp  = *reinterpret_cast<const u64t*>(qr + 2 * dp);
                const u64t kp0 = *reinterpret_cast<const u64t*>(k0r + 2 * dp);
                const u64t kp1 = *reinterpret_cast<const u64t*>(k1r + 2 * dp);
                fma_x2(acc0, qp, kp0);
                fma_x2(acc1, qp, kp1);
            }
            const float2 a0 = unpack_ff(acc0);
            const float2 a1 = unpack_ff(acc1);
            s[qi * 28 + k0]     = (a0.x + a0.y) * 0.125f;
            s[qi * 28 + k0 + 1] = (a1.x + a1.y) * 0.125f;
        }
        if (tid < 26) {
            float acc = sw[96];
            #pragma unroll
            for (int j = 0; j < 32; j++)
                acc += __bfloat162float(g_qkvb[((size_t)b * 26 + tid) * NQKV + 1536 + h * 32 + j]) * sw[j];
            qvd[tid] = acc;
        }
        __syncthreads();

        // softmax over k
        if (tid < 26) {
            float mx = -1e30f;
            for (int k = 0; k < 26; k++) mx = fmaxf(mx, s[tid * 28 + k]);
            float sum = 0.f;
            for (int k = 0; k < 26; k++) {
                float e = expf(s[tid * 28 + k] - mx);
                s[tid * 28 + k] = e; sum += e;
            }
            float inv = 1.f / sum;
            for (int k = 0; k < 26; k++) s[tid * 28 + k] *= inv;
        }
        __syncthreads();

        // fused: comp logits + softmax-r (width-8 shfl) + wT write
        // all 256 threads converged; qi clamped for lanes beyond 208
        {
            const int qi_raw = tid >> 3;
            const int r = tid & 7;
            const int qi = (qi_raw < 26) ? qi_raw : 0;
            float acc = qvd[qi];
            #pragma unroll
            for (int k = 0; k < 26; k++) acc += s[qi * 28 + k] * vw[k * 8 + r];
            // softmax over the 8 r-lanes
            float mx = acc;
            #pragma unroll
            for (int o = 4; o > 0; o >>= 1)
                mx = fmaxf(mx, __shfl_xor_sync(0xffffffffu, mx, o, 8));
            float e = expf(acc - mx);
            float sum = e;
            #pragma unroll
            for (int o = 4; o > 0; o >>= 1)
                sum += __shfl_xor_sync(0xffffffffu, sum, o, 8);
            const float cval = e / sum;
            if (qi_raw < 26) {
                #pragma unroll
                for (int k = 0; k < 26; k++)
                    wT[(k * 8 + r) * 28 + qi_raw] = s[qi_raw * 28 + k] * cval;
            }
        }
        __syncthreads();

        // output phase 1: 224 threads = 7 qg x 16 dq x 2 j-halves; 104 j each, f32x2 FMA
        u64t oac[4][2];
        #pragma unroll
        for (int a = 0; a < 4; a++) { oac[a][0] = 0ull; oac[a][1] = 0ull; }
        const int qg = tid >> 5;
        const int dq = ((tid >> 1) & 15) << 2;
        const int jh = tid & 1;
        if (tid < 224) {
            const int q0 = qg * 4;
            const int j0 = jh * 104;
            #pragma unroll 4
            for (int jj = 0; jj < 104; jj++) {
                const int j = j0 + jj;
                const float4 w4 = *reinterpret_cast<const float4*>(wT + j * 28 + q0);
                const u64t v01 = bf2_to_fx2(vsb[j * 32 + (dq >> 1)]);
                const u64t v23 = bf2_to_fx2(vsb[j * 32 + (dq >> 1) + 1]);
                const u64t w0 = pack_ff(w4.x, w4.x);
                const u64t w1 = pack_ff(w4.y, w4.y);
                const u64t w2 = pack_ff(w4.z, w4.z);
                const u64t w3 = pack_ff(w4.w, w4.w);
                fma_x2(oac[0][0], w0, v01); fma_x2(oac[0][1], w0, v23);
                fma_x2(oac[1][0], w1, v01); fma_x2(oac[1][1], w1, v23);
                fma_x2(oac[2][0], w2, v01); fma_x2(oac[2][1], w2, v23);
                fma_x2(oac[3][0], w3, v01); fma_x2(oac[3][1], w3, v23);
            }
        }
        float oacc[4][4];
        #pragma unroll
        for (int a = 0; a < 4; a++) {
            const float2 p01 = unpack_ff(oac[a][0]);
            const float2 p23 = unpack_ff(oac[a][1]);
            oacc[a][0] = p01.x; oacc[a][1] = p01.y;
            oacc[a][2] = p23.x; oacc[a][3] = p23.y;
        }
        if (tid < 224 && jh == 1) {
            const int idx = qg * 16 + (dq >> 2);
            #pragma unroll
            for (int a = 0; a < 4; a++)
                #pragma unroll
                for (int d2 = 0; d2 < 4; d2++)
                    scratch[(a * 4 + d2) * 112 + idx] = oacc[a][d2];
        }
        __syncthreads();

        // output phase 2: jh==0 threads combine + store
        if (tid < 224 && jh == 0) {
            const int idx = qg * 16 + (dq >> 2);
            const int q0 = qg * 4;
            #pragma unroll
            for (int a = 0; a < 4; a++) {
                const int q = q0 + a;
                if (q < 26) {
                    float r0 = oacc[a][0] + scratch[(a * 4 + 0) * 112 + idx];
                    float r1 = oacc[a][1] + scratch[(a * 4 + 1) * 112 + idx];
                    float r2 = oacc[a][2] + scratch[(a * 4 + 2) * 112 + idx];
                    float r3 = oacc[a][3] + scratch[(a * 4 + 3) * 112 + idx];
                    bf16* dst = g_o + ((size_t)b * 26 + q) * 512 + h * 64 + dq;
                    *(__nv_bfloat162*)(dst) =
                        __nv_bfloat162(__float2bfloat16(r0), __float2bfloat16(r1));
                    *(__nv_bfloat162*)(dst + 2) =
                        __nv_bfloat162(__float2bfloat16(r2), __float2bfloat16(r3));
                }
            }
        }
        __syncthreads();
    }
}

// ---------------- classifier + log_softmax ----------------
__global__ void __launch_bounds__(256) cls_kernel(const float* __restrict__ out_w,
                                                  const float* __restrict__ out_b,
                                                  float* __restrict__ out) {
    const int warp = threadIdx.x >> 5;
    const int lane = threadIdx.x & 31;
    const int b = blockIdx.x * 8 + warp;
    const float* xr = g_x + (size_t)b * SEQ * DMODEL;
    float acc[10] = {};
    for (int d = lane; d < DMODEL; d += 32) {
        float xv = xr[d];
        #pragma unroll
        for (int c = 0; c < 10; c++) acc[c] = fmaf(xv, out_w[d * 10 + c], acc[c]);
    }
    #pragma unroll
    for (int c = 0; c < 10; c++)
        #pragma unroll
        for (int o = 16; o > 0; o >>= 1)
            acc[c] += __shfl_xor_sync(0xffffffffu, acc[c], o);
    if (lane == 0) {
        float y[10], mx = -1e30f;
        #pragma unroll
        for (int c = 0; c < 10; c++) { y[c] = acc[c] + out_b[c]; mx = fmaxf(mx, y[c]); }
        float sum = 0.f;
        #pragma unroll
        for (int c = 0; c < 10; c++) sum += expf(y[c] - mx);
        float lse = logf(sum) + mx;
        #pragma unroll
        for (int c = 0; c < 10; c++) out[b * 10 + c] = y[c] - lse;
    }
}

// ---------------- host orchestration ----------------
extern "C" void kernel_launch(void* const* d_in, const int* in_sizes, int n_in,
                              void* d_out, int out_size) {
    const float* img      = (const float*)d_in[0];
    const float* qst      = (const float*)d_in[1];
    const float* conv_w   = (const float*)d_in[2];
    const float* conv_b   = (const float*)d_in[3];
    const float* qrep_w   = (const float*)d_in[4];
    const float* qrep_b   = (const float*)d_in[5];
    const float* cls_tok  = (const float*)d_in[6];
    const float* map_w    = (const float*)d_in[7];
    const float* map_b    = (const float*)d_in[8];
    const float* norm1_g  = (const float*)d_in[9];
    const float* norm1_b  = (const float*)d_in[10];
    const float* norm2_g  = (const float*)d_in[11];
    const float* norm2_b  = (const float*)d_in[12];
    const float* q_w      = (const float*)d_in[13];
    const float* q_b      = (const float*)d_in[14];
    const float* k_w      = (const float*)d_in[15];
    const float* k_b      = (const float*)d_in[16];
    const float* v_w      = (const float*)d_in[17];
    const float* v_b      = (const float*)d_in[18];
    const float* qv_w     = (const float*)d_in[19];
    const float* qv_b     = (const float*)d_in[20];
    const float* score_w  = (const float*)d_in[21];
    const float* score_b  = (const float*)d_in[22];
    const float* final_w  = (const float*)d_in[23];
    const float* final_b  = (const float*)d_in[24];
    const float* ffn1_w   = (const float*)d_in[25];
    const float* ffn1_b   = (const float*)d_in[26];
    const float* ffn2_w   = (const float*)d_in[27];
    const float* ffn2_b   = (const float*)d_in[28];
    const float* out_w    = (const float*)d_in[29];
    const float* out_b    = (const float*)d_in[30];

    bf16 *p_im2col, *p_wc, *p_mapT, *p_wqkv, *p_finalT,
         *p_ffn1T, *p_ffn2T, *p_xin, *p_h, *p_qkvb, *p_o, *p_t;
    float *p_bqkv, *p_pemb, *p_x;
    cudaGetSymbolAddress((void**)&p_im2col, g_im2col);
    cudaGetSymbolAddress((void**)&p_wc,     g_wc);
    cudaGetSymbolAddress((void**)&p_mapT,   g_mapT);
    cudaGetSymbolAddress((void**)&p_wqkv,   g_wqkv);
    cudaGetSymbolAddress((void**)&p_finalT, g_finalT);
    cudaGetSymbolAddress((void**)&p_ffn1T,  g_ffn1T);
    cudaGetSymbolAddress((void**)&p_ffn2T,  g_ffn2T);
    cudaGetSymbolAddress((void**)&p_xin,    g_xin);
    cudaGetSymbolAddress((void**)&p_h,      g_h);
    cudaGetSymbolAddress((void**)&p_qkvb,   g_qkvb);
    cudaGetSymbolAddress((void**)&p_o,      g_o);
    cudaGetSymbolAddress((void**)&p_t,      g_t);
    cudaGetSymbolAddress((void**)&p_bqkv,   g_bqkv);
    cudaGetSymbolAddress((void**)&p_pemb,   g_pemb);
    cudaGetSymbolAddress((void**)&p_x,      g_x);

    cudaFuncSetAttribute(gemm_tc, cudaFuncAttributeMaxDynamicSharedMemorySize, GEMM_SMEM_BYTES);
    cudaFuncSetAttribute(attn_kernel, cudaFuncAttributeMaxDynamicSharedMemorySize,
                         ATTN_SMEM_FLOATS * (int)sizeof(float));

    // ---- packing / front end ----
    pack_all_kernel<<<10457, 256>>>(conv_w, q_w, k_w, v_w, qv_w, q_b, k_b, v_b, qv_b,
                                    map_w, final_w, ffn1_w, ffn2_w);
    im2col_kernel<<<BATCH * NPATCH, 256>>>(img);

    // conv: [6400,704] x [256,704]^T
    gemm_tc<<<dim3(2, 100), 256, GEMM_SMEM_BYTES>>>(
        p_im2col, p_wc, conv_b, nullptr, p_pemb, nullptr, 6400, HEMB, CONVKP, 0);
    assemble_kernel<<<NROWS * DMODEL / 256, 256>>>(cls_tok, qst, qrep_w, qrep_b);
    // map: [6656,512] x [512,512]^T
    gemm_tc<<<dim3(4, 104), 256, GEMM_SMEM_BYTES>>>(
        p_xin, p_mapT, map_b, nullptr, p_x, nullptr, NROWS, DMODEL, DMODEL, 0);

    // ---- 4 transformer iterations ----
    for (int it = 0; it < 4; it++) {
        ln_kernel<<<NROWS / 8, 256>>>(norm1_g, norm1_b);
        gemm_tc<<<dim3(14, 104), 256, GEMM_SMEM_BYTES>>>(
            p_h, p_wqkv, p_bqkv, nullptr, nullptr, p_qkvb, NROWS, NQKV, DMODEL, 3);
        attn_kernel<<<4 * BATCH, 256, ATTN_SMEM_FLOATS * (int)sizeof(float)>>>(score_w, score_b);
        gemm_tc<<<dim3(4, 104), 256, GEMM_SMEM_BYTES>>>(
            p_o, p_finalT, final_b, p_x, p_x, nullptr, NROWS, DMODEL, DMODEL, 2);
        ln_kernel<<<NROWS / 8, 256>>>(norm2_g, norm2_b);
        gemm_tc<<<dim3(8, 104), 256, GEMM_SMEM_BYTES>>>(
            p_h, p_ffn1T, ffn1_b, nullptr, nullptr, p_t, NROWS, 2 * DMODEL, DMODEL, 1);
        gemm_tc<<<dim3(4, 104), 256, GEMM_SMEM_BYTES>>>(
            p_t, p_ffn2T, ffn2_b, p_x, p_x, nullptr, NROWS, DMODEL, 2 * DMODEL, 2);
    }

    // ---- classifier ----
    cls_kernel<<<BATCH / 8, 256>>>(out_w, out_b, (float*)d_out);
}

// round 15
// speedup vs baseline: 1.0681x; 1.0381x over previous
#include <cuda_runtime.h>
#include <cuda_bf16.h>
#include <math.h>
#include <stdint.h>

// ---------------- constants ----------------
#define BATCH   256
#define SEQ     26
#define DMODEL  512
#define HEMB    256
#define NHEADS  8
#define NROWS   (BATCH*SEQ)     // 6656
#define NPATCH  25
#define CONVK   675             // 3*15*15
#define CONVKP  704             // padded to multiple of 64
#define NQKV    1792            // 512+512+512+256 fused projection width

typedef __nv_bfloat16 bf16;

// ---------------- scratch (device globals; no runtime allocation) ----------------
__device__ bf16  g_im2col[BATCH*NPATCH*CONVKP];
__device__ bf16  g_wc[HEMB*CONVKP];          // [N=256][K=704]
__device__ bf16  g_mapT[DMODEL*DMODEL];      // [N=512][K=512]
__device__ bf16  g_wqkv[NQKV*DMODEL];        // [N=1792][K=512]
__device__ bf16  g_finalT[DMODEL*DMODEL];
__device__ bf16  g_ffn1T[2*DMODEL*DMODEL];   // [N=1024][K=512]
__device__ bf16  g_ffn2T[DMODEL*2*DMODEL];   // [N=512][K=1024]
__device__ float g_bqkv[NQKV];
__device__ float g_pe[NPATCH*HEMB];
__device__ float g_pemb[BATCH*NPATCH*HEMB];
__device__ float g_que[BATCH*HEMB];
__device__ bf16  g_xin[NROWS*DMODEL];
__device__ float g_x[NROWS*DMODEL];
__device__ bf16  g_h[NROWS*DMODEL];
__device__ bf16  g_qkvb[NROWS*NQKV];         // bf16 qkv output
__device__ bf16  g_o[NROWS*DMODEL];
__device__ bf16  g_t[NROWS*2*DMODEL];

// ---------------- helpers ----------------
__device__ __forceinline__ uint32_t smem_u32(const void* p) {
    uint32_t a;
    asm("{ .reg .u64 t; cvta.to.shared.u64 t, %1; cvt.u32.u64 %0, t; }" : "=r"(a) : "l"(p));
    return a;
}
__device__ __forceinline__ void mma_bf16(float* d, const uint32_t* a, const uint32_t* b) {
    asm volatile(
        "mma.sync.aligned.m16n8k16.row.col.f32.bf16.bf16.f32 "
        "{%0,%1,%2,%3}, {%4,%5,%6,%7}, {%8,%9}, {%0,%1,%2,%3};"
        : "+f"(d[0]), "+f"(d[1]), "+f"(d[2]), "+f"(d[3])
        : "r"(a[0]), "r"(a[1]), "r"(a[2]), "r"(a[3]), "r"(b[0]), "r"(b[1]));
}
__device__ __forceinline__ void ldmatrix_x4(uint32_t* r, uint32_t addr) {
    asm volatile("ldmatrix.sync.aligned.m8n8.x4.shared.b16 {%0,%1,%2,%3}, [%4];"
                 : "=r"(r[0]), "=r"(r[1]), "=r"(r[2]), "=r"(r[3]) : "r"(addr));
}
__device__ __forceinline__ void cp_async16(uint32_t dst, const void* src) {
    asm volatile("cp.async.cg.shared.global [%0], [%1], 16;" :: "r"(dst), "l"(src));
}
__device__ __forceinline__ float2 bf2_to_f2(uint32_t u) {
    __nv_bfloat162 h = *reinterpret_cast<__nv_bfloat162*>(&u);
    return __bfloat1622float2(h);
}
// packed f32x2 helpers (sm_103a FFMA2 path)
typedef unsigned long long u64t;
__device__ __forceinline__ u64t pack_ff(float lo, float hi) {
    u64t r;
    asm("mov.b64 %0, {%1, %2};" : "=l"(r) : "f"(lo), "f"(hi));
    return r;
}
__device__ __forceinline__ void fma_x2(u64t& d, u64t a, u64t b) {
    asm("fma.rn.f32x2 %0, %1, %2, %3;" : "=l"(d) : "l"(a), "l"(b), "l"(d));
}
__device__ __forceinline__ float2 unpack_ff(u64t v) {
    float lo, hi;
    asm("mov.b64 {%0, %1}, %2;" : "=f"(lo), "=f"(hi) : "l"(v));
    return make_float2(lo, hi);
}
__device__ __forceinline__ u64t bf2_to_fx2(uint32_t u) {
    uint32_t lo = u << 16;
    uint32_t hi = u & 0xffff0000u;
    u64t r;
    asm("mov.b64 %0, {%1, %2};" : "=l"(r) : "r"(lo), "r"(hi));
    return r;
}

// ---------------- bf16 mma.sync GEMM, 64x128 tile, 2-stage cp.async, 3 CTAs/SM ----------------
#define BM 64
#define BN 128
#define BK 64
#define TS 72
#define A_STAGE_BYTES (64 * TS * 2)      // 9216
#define B_STAGE_BYTES (128 * TS * 2)     // 18432
#define GEMM_SMEM_BYTES (2 * (A_STAGE_BYTES + B_STAGE_BYTES))   // 55296

__global__ void __launch_bounds__(256, 3) gemm_tc(
    const bf16* __restrict__ A, const bf16* __restrict__ B,
    const float* __restrict__ bias, const float* __restrict__ Res,
    float* __restrict__ C, bf16* __restrict__ Cb,
    int M, int N, int K, int mode)
{
    extern __shared__ bf16 smem[];
    const uint32_t as_u = smem_u32(smem);
    const uint32_t bs_u = as_u + 2 * A_STAGE_BYTES;

    const int bm = blockIdx.y * BM;
    const int bn = blockIdx.x * BN;
    const int tid = threadIdx.x;
    const int lane = tid & 31;
    const int wid = tid >> 5;
    const int wm = (wid & 1) * 32;
    const int wn = (wid >> 1) * 32;

    const int rbase = tid >> 3;
    const int kq = (tid & 7) << 3;
    const uint32_t sO = (uint32_t)(rbase * TS + kq) * 2;

    const bf16* pA = A + (size_t)(bm + rbase) * K + kq;
    const bf16* pB = B + (size_t)(bn + rbase) * K + kq;
    const size_t rowstep = (size_t)32 * K;

    float acc[2][4][4];
    #pragma unroll
    for (int mi = 0; mi < 2; mi++)
        #pragma unroll
        for (int ni = 0; ni < 4; ni++)
            #pragma unroll
            for (int r = 0; r < 4; r++) acc[mi][ni][r] = 0.0f;

    const int nchunks = K / BK;

#define ISSUE_STAGE(s)                                                   \
    do {                                                                 \
        const uint32_t ab = as_u + (uint32_t)(s) * A_STAGE_BYTES + sO;   \
        const uint32_t bb = bs_u + (uint32_t)(s) * B_STAGE_BYTES + sO;   \
        cp_async16(ab,         pA);                                      \
        cp_async16(ab + 4608,  pA + rowstep);                            \
        cp_async16(bb,         pB);                                      \
        cp_async16(bb + 4608,  pB + rowstep);                            \
        cp_async16(bb + 9216,  pB + 2 * rowstep);                        \
        cp_async16(bb + 13824, pB + 3 * rowstep);                        \
        asm volatile("cp.async.commit_group;" ::: "memory");             \
        pA += BK; pB += BK;                                              \
    } while (0)

    ISSUE_STAGE(0);
    if (nchunks > 1) ISSUE_STAGE(1);

    const int a_row = (lane & 15);
    const int a_koff = (lane >> 4) << 3;
    const int b_m = lane >> 3;
    const int b_row = ((b_m >> 1) << 3) + (lane & 7);
    const int b_koff = (b_m & 1) << 3;

    for (int c = 0; c < nchunks; c++) {
        if (c + 1 < nchunks) asm volatile("cp.async.wait_group 1;" ::: "memory");
        else                 asm volatile("cp.async.wait_group 0;" ::: "memory");
        __syncthreads();

        const uint32_t a_u = as_u + (uint32_t)(c & 1) * A_STAGE_BYTES;
        const uint32_t b_u = bs_u + (uint32_t)(c & 1) * B_STAGE_BYTES;

        #pragma unroll
        for (int kk = 0; kk < 4; kk++) {
            const int kb = kk * 16;
            uint32_t afr[2][4], bfr[2][4];
            #pragma unroll
            for (int mi = 0; mi < 2; mi++) {
                const uint32_t addr = a_u +
                    (((wm + mi * 16 + a_row) * TS + kb + a_koff) << 1);
                ldmatrix_x4(afr[mi], addr);
            }
            #pragma unroll
            for (int nip = 0; nip < 2; nip++) {
                const uint32_t addr = b_u +
                    (((wn + nip * 16 + b_row) * TS + kb + b_koff) << 1);
                ldmatrix_x4(bfr[nip], addr);
            }
            #pragma unroll
            for (int mi = 0; mi < 2; mi++)
                #pragma unroll
                for (int nip = 0; nip < 2; nip++) {
                    mma_bf16(acc[mi][2 * nip],     afr[mi], &bfr[nip][0]);
                    mma_bf16(acc[mi][2 * nip + 1], afr[mi], &bfr[nip][2]);
                }
        }
        __syncthreads();
        if (c + 2 < nchunks) {
            ISSUE_STAGE(c & 1);
        }
    }
#undef ISSUE_STAGE

    const int g = lane >> 2;
    const int tig = lane & 3;
    #pragma unroll
    for (int mi = 0; mi < 2; mi++) {
        const int r0 = bm + wm + mi * 16 + g;
        const int r1 = r0 + 8;
        #pragma unroll
        for (int ni = 0; ni < 4; ni++) {
            const int col = bn + wn + ni * 8 + tig * 2;
            const float b0 = bias[col], b1 = bias[col + 1];
            float v0 = acc[mi][ni][0] + b0;
            float v1 = acc[mi][ni][1] + b1;
            float v2 = acc[mi][ni][2] + b0;
            float v3 = acc[mi][ni][3] + b1;
            if (mode & 1) {
                if (mode == 1) {
                    v0 = fmaxf(v0, 0.f); v1 = fmaxf(v1, 0.f);
                    v2 = fmaxf(v2, 0.f); v3 = fmaxf(v3, 0.f);
                }
                *(__nv_bfloat162*)(Cb + (size_t)r0 * N + col) =
                    __nv_bfloat162(__float2bfloat16(v0), __float2bfloat16(v1));
                *(__nv_bfloat162*)(Cb + (size_t)r1 * N + col) =
                    __nv_bfloat162(__float2bfloat16(v2), __float2bfloat16(v3));
            } else {
                if (mode == 2) {
                    float2 s0 = *reinterpret_cast<const float2*>(Res + (size_t)r0 * N + col);
                    float2 s1 = *reinterpret_cast<const float2*>(Res + (size_t)r1 * N + col);
                    v0 += s0.x; v1 += s0.y; v2 += s1.x; v3 += s1.y;
                }
                *reinterpret_cast<float2*>(C + (size_t)r0 * N + col) = make_float2(v0, v1);
                *reinterpret_cast<float2*>(C + (size_t)r1 * N + col) = make_float2(v2, v3);
            }
        }
    }
}

// ---------------- one merged packing kernel (incl. positional encoding) ----------------
__global__ void pack_all_kernel(
    const float* __restrict__ conv_w,
    const float* __restrict__ q_w, const float* __restrict__ k_w,
    const float* __restrict__ v_w, const float* __restrict__ qv_w,
    const float* __restrict__ q_b, const float* __restrict__ k_b,
    const float* __restrict__ v_b, const float* __restrict__ qv_b,
    const float* __restrict__ map_w, const float* __restrict__ final_w,
    const float* __restrict__ ffn1_w, const float* __restrict__ ffn2_w)
{
    int idx = blockIdx.x * 256 + threadIdx.x;
    if (idx < 180224) {
        int n = idx / CONVKP, k = idx % CONVKP;
        g_wc[idx] = (k < CONVK) ? __float2bfloat16(conv_w[(size_t)n * CONVK + k])
                                : __float2bfloat16(0.f);
        return;
    }
    idx -= 180224;
    if (idx < 917504) {
        int n = idx / DMODEL, k = idx % DMODEL;
        float w;
        if (n < 512)       w = q_w[(size_t)k * 512 + n];
        else if (n < 1024) w = k_w[(size_t)k * 512 + (n - 512)];
        else if (n < 1536) w = v_w[(size_t)k * 512 + (n - 1024)];
        else               w = qv_w[(size_t)k * 256 + (n - 1536)];
        g_wqkv[idx] = __float2bfloat16(w);
        if (k == 0) {
            float b;
            if (n < 512)       b = q_b[n];
            else if (n < 1024) b = k_b[n - 512];
            else if (n < 1536) b = v_b[n - 1024];
            else               b = qv_b[n - 1536];
            g_bqkv[n] = b;
        }
        return;
    }
    idx -= 917504;
    if (idx < 262144) {
        int n = idx / 512, k = idx % 512;
        g_mapT[idx] = __float2bfloat16(map_w[(size_t)k * 512 + n]);
        return;
    }
    idx -= 262144;
    if (idx < 262144) {
        int n = idx / 512, k = idx % 512;
        g_finalT[idx] = __float2bfloat16(final_w[(size_t)k * 512 + n]);
        return;
    }
    idx -= 262144;
    if (idx < 524288) {
        int n = idx / 512, k = idx % 512;
        g_ffn1T[idx] = __float2bfloat16(ffn1_w[(size_t)k * 1024 + n]);
        return;
    }
    idx -= 524288;
    if (idx < 524288) {
        int n = idx / 1024, k = idx % 1024;
        g_ffn2T[idx] = __float2bfloat16(ffn2_w[(size_t)k * 512 + n]);
        return;
    }
    idx -= 524288;
    if (idx < 6400) {                    // positional encoding (float64 formula)
        const int pos = idx / HEMB;
        const int d = idx % HEMB;
        const int j = d >> 1;
        const double n = 1.0 / (1.0 + exp(-1.0));
        double val;
        if ((d & 1) == 0)
            val = sin((double)pos * pow(10000.0, -(double)j / 64.0));
        else
            val = cos((double)pos * pow(10000.0, -(double)(2 * j + 1) / 128.0));
        g_pe[pos * HEMB + d] = (float)(n * val);
    }
}

// ---------------- que projection: one pass, 256x256 ----------------
__global__ void que_kernel(const float* __restrict__ qst,
                           const float* __restrict__ qrep_w,
                           const float* __restrict__ qrep_b) {
    __shared__ float qsh[18];
    const int b = blockIdx.x;
    const int c = threadIdx.x;
    if (c < 18) qsh[c] = qst[b * 18 + c];
    __syncthreads();
    float acc = qrep_b[c];
    #pragma unroll
    for (int j = 0; j < 18; j++)
        acc = fmaf(qsh[j], qrep_w[j * HEMB + c], acc);
    g_que[b * HEMB + c] = acc;
}

// ---------------- im2col (vectorized: 8 bf16 per thread -> uint4 store) ----------------
__global__ void im2col_kernel(const float* __restrict__ img) {
    const int row = blockIdx.x;
    const int b = row / NPATCH;
    const int patch = row % NPATCH;
    const int ph = patch / 5, pw = patch % 5;
    const int tid = threadIdx.x;
    if (tid < 88) {                       // 88 * 8 = 704
        const int t0 = tid * 8;
        bf16 vals[8];
        #pragma unroll
        for (int e = 0; e < 8; e++) {
            const int t = t0 + e;
            float v = 0.0f;
            if (t < CONVK) {
                const int c = t / 225;
                const int rem = t % 225;
                const int ky = rem / 15, kx = rem % 15;
                v = img[(((size_t)b * 3 + c) * 75 + ph * 15 + ky) * 75 + pw * 15 + kx];
            }
            vals[e] = __float2bfloat16(v);
        }
        *reinterpret_cast<uint4*>(g_im2col + (size_t)row * CONVKP + t0) =
            *reinterpret_cast<const uint4*>(vals);
    }
}

// ---------------- assemble x_in[6656,512] (bf16), 2 cols/thread, que precomputed ----------------
__global__ void assemble_kernel(const float* __restrict__ cls_token) {
    const int row = blockIdx.x;                 // one block per row
    const int tid = threadIdx.x;                // 256 threads x 2 cols
    const int col = tid << 1;
    const int b = row / SEQ;
    const int s = row % SEQ;
    float v0, v1;
    if (col < HEMB) {
        if (s == 0) {
            v0 = cls_token[col]; v1 = cls_token[col + 1];
        } else {
            const float2 pm = *reinterpret_cast<const float2*>(
                g_pemb + ((size_t)b * NPATCH + s - 1) * HEMB + col);
            const float2 pe = *reinterpret_cast<const float2*>(
                g_pe + (s - 1) * HEMB + col);
            v0 = pm.x + pe.x; v1 = pm.y + pe.y;
        }
    } else {
        const float2 q = *reinterpret_cast<const float2*>(
            g_que + (size_t)b * HEMB + (col - HEMB));
        v0 = q.x; v1 = q.y;
    }
    *(__nv_bfloat162*)(g_xin + (size_t)row * DMODEL + col) =
        __nv_bfloat162(__float2bfloat16(v0), __float2bfloat16(v1));
}

// ---------------- LayerNorm: fp32 in, bf16 out ----------------
__global__ void __launch_bounds__(256) ln_kernel(const float* __restrict__ g,
                                                 const float* __restrict__ bta) {
    const int warp = threadIdx.x >> 5;
    const int lane = threadIdx.x & 31;
    const int row = blockIdx.x * 8 + warp;
    const float* xr = g_x + (size_t)row * DMODEL;
    float vals[16];
    float s = 0.f;
    #pragma unroll
    for (int w = 0; w < 4; w++) {
        float4 t = *reinterpret_cast<const float4*>(xr + w * 128 + lane * 4);
        vals[w * 4 + 0] = t.x; vals[w * 4 + 1] = t.y;
        vals[w * 4 + 2] = t.z; vals[w * 4 + 3] = t.w;
        s += t.x + t.y + t.z + t.w;
    }
    #pragma unroll
    for (int o = 16; o > 0; o >>= 1) s += __shfl_xor_sync(0xffffffffu, s, o);
    const float mean = s * (1.0f / DMODEL);
    float sq = 0.f;
    #pragma unroll
    for (int i = 0; i < 16; i++) { float d = vals[i] - mean; sq += d * d; }
    #pragma unroll
    for (int o = 16; o > 0; o >>= 1) sq += __shfl_xor_sync(0xffffffffu, sq, o);
    const float rstd = rsqrtf(sq * (1.0f / DMODEL) + 1e-5f);
    bf16* hr = g_h + (size_t)row * DMODEL;
    #pragma unroll
    for (int w = 0; w < 4; w++) {
        float o0 = (vals[w * 4 + 0] - mean) * rstd * g[w * 128 + lane * 4 + 0] + bta[w * 128 + lane * 4 + 0];
        float o1 = (vals[w * 4 + 1] - mean) * rstd * g[w * 128 + lane * 4 + 1] + bta[w * 128 + lane * 4 + 1];
        float o2 = (vals[w * 4 + 2] - mean) * rstd * g[w * 128 + lane * 4 + 2] + bta[w * 128 + lane * 4 + 2];
        float o3 = (vals[w * 4 + 3] - mean) * rstd * g[w * 128 + lane * 4 + 3] + bta[w * 128 + lane * 4 + 3];
        *(__nv_bfloat162*)(hr + w * 128 + lane * 4)     = __nv_bfloat162(__float2bfloat16(o0), __float2bfloat16(o1));
        *(__nv_bfloat162*)(hr + w * 128 + lane * 4 + 2) = __nv_bfloat162(__float2bfloat16(o2), __float2bfloat16(o3));
    }
}

// ---------------- compositional attention: 4 CTAs per batch (2 heads each) ----------------
#define ATTN_SMEM_FLOATS (6656 + 5824 + 1716 + 1716 + 728 + 208 + 32 + 97)
__global__ void __launch_bounds__(256) attn_kernel(const float* __restrict__ score_w,
                                                   const float* __restrict__ score_b) {
    extern __shared__ float sm[];
    uint32_t* vsb = (uint32_t*)sm;       // 26*256 u32: v bf16x2, [k*512 + r*64 + d]
    float* wT   = sm + 6656;             // [j=208][q pad 28]
    float* qs   = wT + 5824;             // [26][66]
    float* ks   = qs + 1716;
    float* s    = ks + 1716;             // [26][28]
    float* vw   = s + 728;               // [208]
    float* qvd  = vw + 208;              // [26]
    float* sw   = qvd + 32;              // [97]
    float* scratch = qs;                 // 16*112 = 1792 <= 3432 (qs+ks)

    const int b = blockIdx.x >> 2;
    const int h0 = (blockIdx.x & 3) * 2;
    const int tid = threadIdx.x;

    if (tid < 96) sw[tid] = score_w[tid];
    if (tid == 96) sw[96] = score_b[0];

    for (int i = tid; i < 26 * 256; i += 256) {
        const int row = i >> 8, cp = (i & 255) << 1;
        vsb[i] = *reinterpret_cast<const uint32_t*>(
            g_qkvb + ((size_t)b * 26 + row) * NQKV + 1024 + cp);
    }
    __syncthreads();

    for (int i = tid; i < 208; i += 256) {
        float acc = 0.f;
        #pragma unroll 8
        for (int dpp = 0; dpp < 32; dpp++) {
            const int dp = (dpp + i) & 31;
            const float2 v = bf2_to_f2(vsb[i * 32 + dp]);
            acc += v.x * sw[32 + dp * 2] + v.y * sw[32 + dp * 2 + 1];
        }
        vw[i] = acc;
    }
    __syncthreads();

    for (int hh = 0; hh < 2; hh++) {
        const int h = h0 + hh;
        for (int i = tid; i < 26 * 32; i += 256) {
            const int qi = i >> 5, dp = (i & 31) << 1;
            const float2 qv = bf2_to_f2(*reinterpret_cast<const uint32_t*>(
                g_qkvb + ((size_t)b * 26 + qi) * NQKV + h * 64 + dp));
            const float2 kv = bf2_to_f2(*reinterpret_cast<const uint32_t*>(
                g_qkvb + ((size_t)b * 26 + qi) * NQKV + 512 + h * 64 + dp));
            qs[qi * 66 + dp] = qv.x; qs[qi * 66 + dp + 1] = qv.y;
            ks[qi * 66 + dp] = kv.x; ks[qi * 66 + dp + 1] = kv.y;
        }
        __syncthreads();

        for (int i = tid; i < 338; i += 256) {
            const int qi = i / 13;
            const int k0 = (i % 13) * 2;
            u64t acc0 = 0ull, acc1 = 0ull;
            const float* qr = qs + qi * 66;
            const float* k0r = ks + k0 * 66;
            const float* k1r = k0r + 66;
            #pragma unroll 8
            for (int dp = 0; dp < 32; dp++) {
                const u64t qp  = *reinterpret_cast<const u64t*>(qr + 2 * dp);
                const u64t kp0 = *reinterpret_cast<const u64t*>(k0r + 2 * dp);
                const u64t kp1 = *reinterpret_cast<const u64t*>(k1r + 2 * dp);
                fma_x2(acc0, qp, kp0);
                fma_x2(acc1, qp, kp1);
            }
            const float2 a0 = unpack_ff(acc0);
            const float2 a1 = unpack_ff(acc1);
            s[qi * 28 + k0]     = (a0.x + a0.y) * 0.125f;
            s[qi * 28 + k0 + 1] = (a1.x + a1.y) * 0.125f;
        }
        if (tid < 26) {
            float acc = sw[96];
            #pragma unroll
            for (int j = 0; j < 32; j++)
                acc += __bfloat162float(g_qkvb[((size_t)b * 26 + tid) * NQKV + 1536 + h * 32 + j]) * sw[j];
            qvd[tid] = acc;
        }
        __syncthreads();

        if (tid < 26) {
            float mx = -1e30f;
            for (int k = 0; k < 26; k++) mx = fmaxf(mx, s[tid * 28 + k]);
            float sum = 0.f;
            for (int k = 0; k < 26; k++) {
                float e = expf(s[tid * 28 + k] - mx);
                s[tid * 28 + k] = e; sum += e;
            }
            float inv = 1.f / sum;
            for (int k = 0; k < 26; k++) s[tid * 28 + k] *= inv;
        }
        __syncthreads();

        // fused: comp logits + softmax-r (width-8 shfl) + wT write
        {
            const int qi_raw = tid >> 3;
            const int r = tid & 7;
            const int qi = (qi_raw < 26) ? qi_raw : 0;
            float acc = qvd[qi];
            #pragma unroll
            for (int k = 0; k < 26; k++) acc += s[qi * 28 + k] * vw[k * 8 + r];
            float mx = acc;
            #pragma unroll
            for (int o = 4; o > 0; o >>= 1)
                mx = fmaxf(mx, __shfl_xor_sync(0xffffffffu, mx, o, 8));
            float e = expf(acc - mx);
            float sum = e;
            #pragma unroll
            for (int o = 4; o > 0; o >>= 1)
                sum += __shfl_xor_sync(0xffffffffu, sum, o, 8);
            const float cval = e / sum;
            if (qi_raw < 26) {
                #pragma unroll
                for (int k = 0; k < 26; k++)
                    wT[(k * 8 + r) * 28 + qi_raw] = s[qi_raw * 28 + k] * cval;
            }
        }
        __syncthreads();

        // output phase 1
        u64t oac[4][2];
        #pragma unroll
        for (int a = 0; a < 4; a++) { oac[a][0] = 0ull; oac[a][1] = 0ull; }
        const int qg = tid >> 5;
        const int dq = ((tid >> 1) & 15) << 2;
        const int jh = tid & 1;
        if (tid < 224) {
            const int q0 = qg * 4;
            const int j0 = jh * 104;
            #pragma unroll 4
            for (int jj = 0; jj < 104; jj++) {
                const int j = j0 + jj;
                const float4 w4 = *reinterpret_cast<const float4*>(wT + j * 28 + q0);
                const u64t v01 = bf2_to_fx2(vsb[j * 32 + (dq >> 1)]);
                const u64t v23 = bf2_to_fx2(vsb[j * 32 + (dq >> 1) + 1]);
                const u64t w0 = pack_ff(w4.x, w4.x);
                const u64t w1 = pack_ff(w4.y, w4.y);
                const u64t w2 = pack_ff(w4.z, w4.z);
                const u64t w3 = pack_ff(w4.w, w4.w);
                fma_x2(oac[0][0], w0, v01); fma_x2(oac[0][1], w0, v23);
                fma_x2(oac[1][0], w1, v01); fma_x2(oac[1][1], w1, v23);
                fma_x2(oac[2][0], w2, v01); fma_x2(oac[2][1], w2, v23);
                fma_x2(oac[3][0], w3, v01); fma_x2(oac[3][1], w3, v23);
            }
        }
        float oacc[4][4];
        #pragma unroll
        for (int a = 0; a < 4; a++) {
            const float2 p01 = unpack_ff(oac[a][0]);
            const float2 p23 = unpack_ff(oac[a][1]);
            oacc[a][0] = p01.x; oacc[a][1] = p01.y;
            oacc[a][2] = p23.x; oacc[a][3] = p23.y;
        }
        if (tid < 224 && jh == 1) {
            const int idx = qg * 16 + (dq >> 2);
            #pragma unroll
            for (int a = 0; a < 4; a++)
                #pragma unroll
                for (int d2 = 0; d2 < 4; d2++)
                    scratch[(a * 4 + d2) * 112 + idx] = oacc[a][d2];
        }
        __syncthreads();

        if (tid < 224 && jh == 0) {
            const int idx = qg * 16 + (dq >> 2);
            const int q0 = qg * 4;
            #pragma unroll
            for (int a = 0; a < 4; a++) {
                const int q = q0 + a;
                if (q < 26) {
                    float r0 = oacc[a][0] + scratch[(a * 4 + 0) * 112 + idx];
                    float r1 = oacc[a][1] + scratch[(a * 4 + 1) * 112 + idx];
                    float r2 = oacc[a][2] + scratch[(a * 4 + 2) * 112 + idx];
                    float r3 = oacc[a][3] + scratch[(a * 4 + 3) * 112 + idx];
                    bf16* dst = g_o + ((size_t)b * 26 + q) * 512 + h * 64 + dq;
                    *(__nv_bfloat162*)(dst) =
                        __nv_bfloat162(__float2bfloat16(r0), __float2bfloat16(r1));
                    *(__nv_bfloat162*)(dst + 2) =
                        __nv_bfloat162(__float2bfloat16(r2), __float2bfloat16(r3));
                }
            }
        }
        __syncthreads();
    }
}

// ---------------- classifier + log_softmax ----------------
__global__ void __launch_bounds__(256) cls_kernel(const float* __restrict__ out_w,
                                                  const float* __restrict__ out_b,
                                                  float* __restrict__ out) {
    const int warp = threadIdx.x >> 5;
    const int lane = threadIdx.x & 31;
    const int b = blockIdx.x * 8 + warp;
    const float* xr = g_x + (size_t)b * SEQ * DMODEL;
    float acc[10] = {};
    for (int d = lane; d < DMODEL; d += 32) {
        float xv = xr[d];
        #pragma unroll
        for (int c = 0; c < 10; c++) acc[c] = fmaf(xv, out_w[d * 10 + c], acc[c]);
    }
    #pragma unroll
    for (int c = 0; c < 10; c++)
        #pragma unroll
        for (int o = 16; o > 0; o >>= 1)
            acc[c] += __shfl_xor_sync(0xffffffffu, acc[c], o);
    if (lane == 0) {
        float y[10], mx = -1e30f;
        #pragma unroll
        for (int c = 0; c < 10; c++) { y[c] = acc[c] + out_b[c]; mx = fmaxf(mx, y[c]); }
        float sum = 0.f;
        #pragma unroll
        for (int c = 0; c < 10; c++) sum += expf(y[c] - mx);
        float lse = logf(sum) + mx;
        #pragma unroll
        for (int c = 0; c < 10; c++) out[b * 10 + c] = y[c] - lse;
    }
}

// ---------------- host orchestration ----------------
extern "C" void kernel_launch(void* const* d_in, const int* in_sizes, int n_in,
                              void* d_out, int out_size) {
    const float* img      = (const float*)d_in[0];
    const float* qst      = (const float*)d_in[1];
    const float* conv_w   = (const float*)d_in[2];
    const float* conv_b   = (const float*)d_in[3];
    const float* qrep_w   = (const float*)d_in[4];
    const float* qrep_b   = (const float*)d_in[5];
    const float* cls_tok  = (const float*)d_in[6];
    const float* map_w    = (const float*)d_in[7];
    const float* map_b    = (const float*)d_in[8];
    const float* norm1_g  = (const float*)d_in[9];
    const float* norm1_b  = (const float*)d_in[10];
    const float* norm2_g  = (const float*)d_in[11];
    const float* norm2_b  = (const float*)d_in[12];
    const float* q_w      = (const float*)d_in[13];
    const float* q_b      = (const float*)d_in[14];
    const float* k_w      = (const float*)d_in[15];
    const float* k_b      = (const float*)d_in[16];
    const float* v_w      = (const float*)d_in[17];
    const float* v_b      = (const float*)d_in[18];
    const float* qv_w     = (const float*)d_in[19];
    const float* qv_b     = (const float*)d_in[20];
    const float* score_w  = (const float*)d_in[21];
    const float* score_b  = (const float*)d_in[22];
    const float* final_w  = (const float*)d_in[23];
    const float* final_b  = (const float*)d_in[24];
    const float* ffn1_w   = (const float*)d_in[25];
    const float* ffn1_b   = (const float*)d_in[26];
    const float* ffn2_w   = (const float*)d_in[27];
    const float* ffn2_b   = (const float*)d_in[28];
    const float* out_w    = (const float*)d_in[29];
    const float* out_b    = (const float*)d_in[30];

    bf16 *p_im2col, *p_wc, *p_mapT, *p_wqkv, *p_finalT,
         *p_ffn1T, *p_ffn2T, *p_xin, *p_h, *p_qkvb, *p_o, *p_t;
    float *p_bqkv, *p_pemb, *p_x;
    cudaGetSymbolAddress((void**)&p_im2col, g_im2col);
    cudaGetSymbolAddress((void**)&p_wc,     g_wc);
    cudaGetSymbolAddress((void**)&p_mapT,   g_mapT);
    cudaGetSymbolAddress((void**)&p_wqkv,   g_wqkv);
    cudaGetSymbolAddress((void**)&p_finalT, g_finalT);
    cudaGetSymbolAddress((void**)&p_ffn1T,  g_ffn1T);
    cudaGetSymbolAddress((void**)&p_ffn2T,  g_ffn2T);
    cudaGetSymbolAddress((void**)&p_xin,    g_xin);
    cudaGetSymbolAddress((void**)&p_h,      g_h);
    cudaGetSymbolAddress((void**)&p_qkvb,   g_qkvb);
    cudaGetSymbolAddress((void**)&p_o,      g_o);
    cudaGetSymbolAddress((void**)&p_t,      g_t);
    cudaGetSymbolAddress((void**)&p_bqkv,   g_bqkv);
    cudaGetSymbolAddress((void**)&p_pemb,   g_pemb);
    cudaGetSymbolAddress((void**)&p_x,      g_x);

    cudaFuncSetAttribute(gemm_tc, cudaFuncAttributeMaxDynamicSharedMemorySize, GEMM_SMEM_BYTES);
    cudaFuncSetAttribute(attn_kernel, cudaFuncAttributeMaxDynamicSharedMemorySize,
                         ATTN_SMEM_FLOATS * (int)sizeof(float));

    // ---- packing / front end ----
    pack_all_kernel<<<10457, 256>>>(conv_w, q_w, k_w, v_w, qv_w, q_b, k_b, v_b, qv_b,
                                    map_w, final_w, ffn1_w, ffn2_w);
    que_kernel<<<BATCH, 256>>>(qst, qrep_w, qrep_b);
    im2col_kernel<<<BATCH * NPATCH, 128>>>(img);

    // conv: [6400,704] x [256,704]^T
    gemm_tc<<<dim3(2, 100), 256, GEMM_SMEM_BYTES>>>(
        p_im2col, p_wc, conv_b, nullptr, p_pemb, nullptr, 6400, HEMB, CONVKP, 0);
    assemble_kernel<<<NROWS, 256>>>(cls_tok);
    // map: [6656,512] x [512,512]^T
    gemm_tc<<<dim3(4, 104), 256, GEMM_SMEM_BYTES>>>(
        p_xin, p_mapT, map_b, nullptr, p_x, nullptr, NROWS, DMODEL, DMODEL, 0);

    // ---- 4 transformer iterations ----
    for (int it = 0; it < 4; it++) {
        ln_kernel<<<NROWS / 8, 256>>>(norm1_g, norm1_b);
        gemm_tc<<<dim3(14, 104), 256, GEMM_SMEM_BYTES>>>(
            p_h, p_wqkv, p_bqkv, nullptr, nullptr, p_qkvb, NROWS, NQKV, DMODEL, 3);
        attn_kernel<<<4 * BATCH, 256, ATTN_SMEM_FLOATS * (int)sizeof(float)>>>(score_w, score_b);
        gemm_tc<<<dim3(4, 104), 256, GEMM_SMEM_BYTES>>>(
            p_o, p_finalT, final_b, p_x, p_x, nullptr, NROWS, DMODEL, DMODEL, 2);
        ln_kernel<<<NROWS / 8, 256>>>(norm2_g, norm2_b);
        gemm_tc<<<dim3(8, 104), 256, GEMM_SMEM_BYTES>>>(
            p_h, p_ffn1T, ffn1_b, nullptr, nullptr, p_t, NROWS, 2 * DMODEL, DMODEL, 1);
        gemm_tc<<<dim3(4, 104), 256, GEMM_SMEM_BYTES>>>(
            p_t, p_ffn2T, ffn2_b, p_x, p_x, nullptr, NROWS, DMODEL, 2 * DMODEL, 2);
    }

    // ---- classifier ----
    cls_kernel<<<BATCH / 8, 256>>>(out_w, out_b, (float*)d_out);
}

// round 16
// speedup vs baseline: 1.0939x; 1.0242x over previous
#include <cuda_runtime.h>
#include <cuda_bf16.h>
#include <math.h>
#include <stdint.h>

// ---------------- constants ----------------
#define BATCH   256
#define SEQ     26
#define DMODEL  512
#define HEMB    256
#define NHEADS  8
#define NROWS   (BATCH*SEQ)     // 6656
#define NPATCH  25
#define CONVK   675             // 3*15*15
#define CONVKP  704             // padded to multiple of 64
#define NQKV    1792            // 512+512+512+256 fused projection width

typedef __nv_bfloat16 bf16;

// ---------------- scratch (device globals; no runtime allocation) ----------------
__device__ bf16  g_im2col[BATCH*NPATCH*CONVKP];
__device__ bf16  g_wc[HEMB*CONVKP];          // [N=256][K=704]
__device__ bf16  g_mapT[DMODEL*DMODEL];      // [N=512][K=512]
__device__ bf16  g_wqkv[NQKV*DMODEL];        // [N=1792][K=512]
__device__ bf16  g_finalT[DMODEL*DMODEL];
__device__ bf16  g_ffn1T[2*DMODEL*DMODEL];   // [N=1024][K=512]
__device__ bf16  g_ffn2T[DMODEL*2*DMODEL];   // [N=512][K=1024]
__device__ float g_bqkv[NQKV];
__device__ float g_pe[NPATCH*HEMB];
__device__ float g_pemb[BATCH*NPATCH*HEMB];
__device__ float g_que[BATCH*HEMB];
__device__ bf16  g_xin[NROWS*DMODEL];
__device__ float g_x[NROWS*DMODEL];
__device__ bf16  g_h[NROWS*DMODEL];
__device__ bf16  g_qkvb[NROWS*NQKV];         // bf16 qkv output
__device__ bf16  g_o[NROWS*DMODEL];
__device__ bf16  g_t[NROWS*2*DMODEL];

// ---------------- helpers ----------------
__device__ __forceinline__ uint32_t smem_u32(const void* p) {
    uint32_t a;
    asm("{ .reg .u64 t; cvta.to.shared.u64 t, %1; cvt.u32.u64 %0, t; }" : "=r"(a) : "l"(p));
    return a;
}
__device__ __forceinline__ void mma_bf16(float* d, const uint32_t* a, const uint32_t* b) {
    asm volatile(
        "mma.sync.aligned.m16n8k16.row.col.f32.bf16.bf16.f32 "
        "{%0,%1,%2,%3}, {%4,%5,%6,%7}, {%8,%9}, {%0,%1,%2,%3};"
        : "+f"(d[0]), "+f"(d[1]), "+f"(d[2]), "+f"(d[3])
        : "r"(a[0]), "r"(a[1]), "r"(a[2]), "r"(a[3]), "r"(b[0]), "r"(b[1]));
}
__device__ __forceinline__ void ldmatrix_x4(uint32_t* r, uint32_t addr) {
    asm volatile("ldmatrix.sync.aligned.m8n8.x4.shared.b16 {%0,%1,%2,%3}, [%4];"
                 : "=r"(r[0]), "=r"(r[1]), "=r"(r[2]), "=r"(r[3]) : "r"(addr));
}
__device__ __forceinline__ void cp_async16(uint32_t dst, const void* src) {
    asm volatile("cp.async.cg.shared.global [%0], [%1], 16;" :: "r"(dst), "l"(src));
}
__device__ __forceinline__ float2 bf2_to_f2(uint32_t u) {
    __nv_bfloat162 h = *reinterpret_cast<__nv_bfloat162*>(&u);
    return __bfloat1622float2(h);
}
// packed f32x2 helpers (sm_103a FFMA2 path)
typedef unsigned long long u64t;
__device__ __forceinline__ u64t pack_ff(float lo, float hi) {
    u64t r;
    asm("mov.b64 %0, {%1, %2};" : "=l"(r) : "f"(lo), "f"(hi));
    return r;
}
__device__ __forceinline__ void fma_x2(u64t& d, u64t a, u64t b) {
    asm("fma.rn.f32x2 %0, %1, %2, %3;" : "=l"(d) : "l"(a), "l"(b), "l"(d));
}
__device__ __forceinline__ float2 unpack_ff(u64t v) {
    float lo, hi;
    asm("mov.b64 {%0, %1}, %2;" : "=f"(lo), "=f"(hi) : "l"(v));
    return make_float2(lo, hi);
}
__device__ __forceinline__ u64t bf2_to_fx2(uint32_t u) {
    uint32_t lo = u << 16;
    uint32_t hi = u & 0xffff0000u;
    u64t r;
    asm("mov.b64 %0, {%1, %2};" : "=l"(r) : "r"(lo), "r"(hi));
    return r;
}

// ---------------- bf16 mma.sync GEMM, 64x128 tile, 2-stage cp.async, 3 CTAs/SM ----------------
#define BM 64
#define BN 128
#define BK 64
#define TS 72
#define A_STAGE_BYTES (64 * TS * 2)      // 9216
#define B_STAGE_BYTES (128 * TS * 2)     // 18432
#define GEMM_SMEM_BYTES (2 * (A_STAGE_BYTES + B_STAGE_BYTES))   // 55296

__global__ void __launch_bounds__(256, 3) gemm_tc(
    const bf16* __restrict__ A, const bf16* __restrict__ B,
    const float* __restrict__ bias, const float* __restrict__ Res,
    float* __restrict__ C, bf16* __restrict__ Cb,
    int M, int N, int K, int mode)
{
    extern __shared__ bf16 smem[];
    const uint32_t as_u = smem_u32(smem);
    const uint32_t bs_u = as_u + 2 * A_STAGE_BYTES;

    const int bm = blockIdx.y * BM;
    const int bn = blockIdx.x * BN;
    const int tid = threadIdx.x;
    const int lane = tid & 31;
    const int wid = tid >> 5;
    const int wm = (wid & 1) * 32;
    const int wn = (wid >> 1) * 32;

    const int rbase = tid >> 3;
    const int kq = (tid & 7) << 3;
    const uint32_t sO = (uint32_t)(rbase * TS + kq) * 2;

    const bf16* pA = A + (size_t)(bm + rbase) * K + kq;
    const bf16* pB = B + (size_t)(bn + rbase) * K + kq;
    const size_t rowstep = (size_t)32 * K;

    float acc[2][4][4];
    #pragma unroll
    for (int mi = 0; mi < 2; mi++)
        #pragma unroll
        for (int ni = 0; ni < 4; ni++)
            #pragma unroll
            for (int r = 0; r < 4; r++) acc[mi][ni][r] = 0.0f;

    const int nchunks = K / BK;

#define ISSUE_STAGE(s)                                                   \
    do {                                                                 \
        const uint32_t ab = as_u + (uint32_t)(s) * A_STAGE_BYTES + sO;   \
        const uint32_t bb = bs_u + (uint32_t)(s) * B_STAGE_BYTES + sO;   \
        cp_async16(ab,         pA);                                      \
        cp_async16(ab + 4608,  pA + rowstep);                            \
        cp_async16(bb,         pB);                                      \
        cp_async16(bb + 4608,  pB + rowstep);                            \
        cp_async16(bb + 9216,  pB + 2 * rowstep);                        \
        cp_async16(bb + 13824, pB + 3 * rowstep);                        \
        asm volatile("cp.async.commit_group;" ::: "memory");             \
        pA += BK; pB += BK;                                              \
    } while (0)

    ISSUE_STAGE(0);
    if (nchunks > 1) ISSUE_STAGE(1);

    const int a_row = (lane & 15);
    const int a_koff = (lane >> 4) << 3;
    const int b_m = lane >> 3;
    const int b_row = ((b_m >> 1) << 3) + (lane & 7);
    const int b_koff = (b_m & 1) << 3;

    for (int c = 0; c < nchunks; c++) {
        if (c + 1 < nchunks) asm volatile("cp.async.wait_group 1;" ::: "memory");
        else                 asm volatile("cp.async.wait_group 0;" ::: "memory");
        __syncthreads();

        const uint32_t a_u = as_u + (uint32_t)(c & 1) * A_STAGE_BYTES;
        const uint32_t b_u = bs_u + (uint32_t)(c & 1) * B_STAGE_BYTES;

        #pragma unroll
        for (int kk = 0; kk < 4; kk++) {
            const int kb = kk * 16;
            uint32_t afr[2][4], bfr[2][4];
            #pragma unroll
            for (int mi = 0; mi < 2; mi++) {
                const uint32_t addr = a_u +
                    (((wm + mi * 16 + a_row) * TS + kb + a_koff) << 1);
                ldmatrix_x4(afr[mi], addr);
            }
            #pragma unroll
            for (int nip = 0; nip < 2; nip++) {
                const uint32_t addr = b_u +
                    (((wn + nip * 16 + b_row) * TS + kb + b_koff) << 1);
                ldmatrix_x4(bfr[nip], addr);
            }
            #pragma unroll
            for (int mi = 0; mi < 2; mi++)
                #pragma unroll
                for (int nip = 0; nip < 2; nip++) {
                    mma_bf16(acc[mi][2 * nip],     afr[mi], &bfr[nip][0]);
                    mma_bf16(acc[mi][2 * nip + 1], afr[mi], &bfr[nip][2]);
                }
        }
        __syncthreads();
        if (c + 2 < nchunks) {
            ISSUE_STAGE(c & 1);
        }
    }
#undef ISSUE_STAGE

    const int g = lane >> 2;
    const int tig = lane & 3;
    #pragma unroll
    for (int mi = 0; mi < 2; mi++) {
        const int r0 = bm + wm + mi * 16 + g;
        const int r1 = r0 + 8;
        #pragma unroll
        for (int ni = 0; ni < 4; ni++) {
            const int col = bn + wn + ni * 8 + tig * 2;
            const float b0 = bias[col], b1 = bias[col + 1];
            float v0 = acc[mi][ni][0] + b0;
            float v1 = acc[mi][ni][1] + b1;
            float v2 = acc[mi][ni][2] + b0;
            float v3 = acc[mi][ni][3] + b1;
            if (mode & 1) {
                if (mode == 1) {
                    v0 = fmaxf(v0, 0.f); v1 = fmaxf(v1, 0.f);
                    v2 = fmaxf(v2, 0.f); v3 = fmaxf(v3, 0.f);
                }
                *(__nv_bfloat162*)(Cb + (size_t)r0 * N + col) =
                    __nv_bfloat162(__float2bfloat16(v0), __float2bfloat16(v1));
                *(__nv_bfloat162*)(Cb + (size_t)r1 * N + col) =
                    __nv_bfloat162(__float2bfloat16(v2), __float2bfloat16(v3));
            } else {
                if (mode == 2) {
                    float2 s0 = *reinterpret_cast<const float2*>(Res + (size_t)r0 * N + col);
                    float2 s1 = *reinterpret_cast<const float2*>(Res + (size_t)r1 * N + col);
                    v0 += s0.x; v1 += s0.y; v2 += s1.x; v3 += s1.y;
                }
                *reinterpret_cast<float2*>(C + (size_t)r0 * N + col) = make_float2(v0, v1);
                *reinterpret_cast<float2*>(C + (size_t)r1 * N + col) = make_float2(v2, v3);
            }
        }
    }
}

// ---------------- tiled transpose pack: dst[n*K+k] = bf16(src[k*N+n]) ----------------
// 32x32 tiles via smem; both global accesses coalesced.
// tile ranges: wqkv 896 (56nx16k) | mapT 256 (16x16) | finalT 256 | ffn1T 512 (32nx16k) | ffn2T 512 (16nx32k)
__global__ void packT_tiled_kernel(
    const float* __restrict__ q_w, const float* __restrict__ k_w,
    const float* __restrict__ v_w, const float* __restrict__ qv_w,
    const float* __restrict__ map_w, const float* __restrict__ final_w,
    const float* __restrict__ ffn1_w, const float* __restrict__ ffn2_w)
{
    __shared__ float tile[32][33];
    int tb = blockIdx.x;
    const float* src; bf16* dst;
    int Nn, Kk, tn, tk;
    if (tb < 896) {            // wqkv: N=1792 (composite), K=512
        tn = tb % 56; tk = tb / 56; Nn = 0; Kk = 512;
        const int n0 = tn * 32;
        // source selected per tile (n-ranges are 32-aligned within sections)
        if (n0 < 512)       { src = q_w;  Nn = 512; }
        else if (n0 < 1024) { src = k_w  - 512;  Nn = 512; }   // offset handled below
        else if (n0 < 1536) { src = v_w  - 1024; Nn = 512; }
        else                { src = qv_w - 1536; Nn = 256; }
        // load: src[k][n] with n = n0_local.. ; use absolute n via adjusted base
        const int tx = threadIdx.x & 31, ty = threadIdx.x >> 5;  // 32x8
        const int nsec = (n0 < 512) ? n0 : (n0 < 1024 ? n0 - 512 : (n0 < 1536 ? n0 - 1024 : n0 - 1536));
        const float* sbase = (n0 < 512) ? q_w : (n0 < 1024 ? k_w : (n0 < 1536 ? v_w : qv_w));
        const int srcN = (n0 < 1536) ? 512 : 256;
        #pragma unroll
        for (int r = 0; r < 4; r++) {
            const int k = tk * 32 + ty + r * 8;
            tile[ty + r * 8][tx] = sbase[(size_t)k * srcN + nsec + tx];
        }
        __syncthreads();
        #pragma unroll
        for (int r = 0; r < 4; r++) {
            const int n = n0 + ty + r * 8;
            g_wqkv[(size_t)n * 512 + tk * 32 + tx] = __float2bfloat16(tile[tx][ty + r * 8]);
        }
        return;
    }
    tb -= 896;
    if (tb < 256)       { src = map_w;   dst = g_mapT;   Nn = 512;  Kk = 512;  tn = tb % 16; tk = tb / 16; }
    else if (tb < 512)  { tb -= 256; src = final_w; dst = g_finalT; Nn = 512;  Kk = 512;  tn = tb % 16; tk = tb / 16; }
    else if (tb < 1024) { tb -= 512; src = ffn1_w;  dst = g_ffn1T;  Nn = 1024; Kk = 512;  tn = tb % 32; tk = tb / 32; }
    else                { tb -= 1024; src = ffn2_w; dst = g_ffn2T;  Nn = 512;  Kk = 1024; tn = tb % 16; tk = tb / 16; }
    const int tx = threadIdx.x & 31, ty = threadIdx.x >> 5;
    #pragma unroll
    for (int r = 0; r < 4; r++) {
        const int k = tk * 32 + ty + r * 8;
        tile[ty + r * 8][tx] = src[(size_t)k * Nn + tn * 32 + tx];
    }
    __syncthreads();
    #pragma unroll
    for (int r = 0; r < 4; r++) {
        const int n = tn * 32 + ty + r * 8;
        dst[(size_t)n * Kk + tk * 32 + tx] = __float2bfloat16(tile[tx][ty + r * 8]);
    }
}

// ---------------- small pack: wc (coalesced) + bias + pe ----------------
// ranges: wc 180224 | bias 1792 | pe 6400  total 188416 = 736*256
__global__ void pack_small_kernel(
    const float* __restrict__ conv_w,
    const float* __restrict__ q_b, const float* __restrict__ k_b,
    const float* __restrict__ v_b, const float* __restrict__ qv_b)
{
    int idx = blockIdx.x * 256 + threadIdx.x;
    if (idx < 180224) {
        int n = idx / CONVKP, k = idx % CONVKP;
        g_wc[idx] = (k < CONVK) ? __float2bfloat16(conv_w[(size_t)n * CONVK + k])
                                : __float2bfloat16(0.f);
        return;
    }
    idx -= 180224;
    if (idx < 1792) {
        float b;
        if (idx < 512)       b = q_b[idx];
        else if (idx < 1024) b = k_b[idx - 512];
        else if (idx < 1536) b = v_b[idx - 1024];
        else                 b = qv_b[idx - 1536];
        g_bqkv[idx] = b;
        return;
    }
    idx -= 1792;
    if (idx < 6400) {
        const int pos = idx / HEMB;
        const int d = idx % HEMB;
        const int j = d >> 1;
        const double n = 1.0 / (1.0 + exp(-1.0));
        double val;
        if ((d & 1) == 0)
            val = sin((double)pos * pow(10000.0, -(double)j / 64.0));
        else
            val = cos((double)pos * pow(10000.0, -(double)(2 * j + 1) / 128.0));
        g_pe[pos * HEMB + d] = (float)(n * val);
    }
}

// ---------------- que projection: one pass, 256x256 ----------------
__global__ void que_kernel(const float* __restrict__ qst,
                           const float* __restrict__ qrep_w,
                           const float* __restrict__ qrep_b) {
    __shared__ float qsh[18];
    const int b = blockIdx.x;
    const int c = threadIdx.x;
    if (c < 18) qsh[c] = qst[b * 18 + c];
    __syncthreads();
    float acc = qrep_b[c];
    #pragma unroll
    for (int j = 0; j < 18; j++)
        acc = fmaf(qsh[j], qrep_w[j * HEMB + c], acc);
    g_que[b * HEMB + c] = acc;
}

// ---------------- im2col (vectorized: 8 bf16 per thread -> uint4 store) ----------------
__global__ void im2col_kernel(const float* __restrict__ img) {
    const int row = blockIdx.x;
    const int b = row / NPATCH;
    const int patch = row % NPATCH;
    const int ph = patch / 5, pw = patch % 5;
    const int tid = threadIdx.x;
    if (tid < 88) {                       // 88 * 8 = 704
        const int t0 = tid * 8;
        bf16 vals[8];
        #pragma unroll
        for (int e = 0; e < 8; e++) {
            const int t = t0 + e;
            float v = 0.0f;
            if (t < CONVK) {
                const int c = t / 225;
                const int rem = t % 225;
                const int ky = rem / 15, kx = rem % 15;
                v = img[(((size_t)b * 3 + c) * 75 + ph * 15 + ky) * 75 + pw * 15 + kx];
            }
            vals[e] = __float2bfloat16(v);
        }
        *reinterpret_cast<uint4*>(g_im2col + (size_t)row * CONVKP + t0) =
            *reinterpret_cast<const uint4*>(vals);
    }
}

// ---------------- assemble x_in[6656,512] (bf16) ----------------
__global__ void assemble_kernel(const float* __restrict__ cls_token) {
    const int row = blockIdx.x;
    const int tid = threadIdx.x;
    const int col = tid << 1;
    const int b = row / SEQ;
    const int s = row % SEQ;
    float v0, v1;
    if (col < HEMB) {
        if (s == 0) {
            v0 = cls_token[col]; v1 = cls_token[col + 1];
        } else {
            const float2 pm = *reinterpret_cast<const float2*>(
                g_pemb + ((size_t)b * NPATCH + s - 1) * HEMB + col);
            const float2 pe = *reinterpret_cast<const float2*>(
                g_pe + (s - 1) * HEMB + col);
            v0 = pm.x + pe.x; v1 = pm.y + pe.y;
        }
    } else {
        const float2 q = *reinterpret_cast<const float2*>(
            g_que + (size_t)b * HEMB + (col - HEMB));
        v0 = q.x; v1 = q.y;
    }
    *(__nv_bfloat162*)(g_xin + (size_t)row * DMODEL + col) =
        __nv_bfloat162(__float2bfloat16(v0), __float2bfloat16(v1));
}

// ---------------- LayerNorm: fp32 in, bf16 out ----------------
__global__ void __launch_bounds__(256) ln_kernel(const float* __restrict__ g,
                                                 const float* __restrict__ bta) {
    const int warp = threadIdx.x >> 5;
    const int lane = threadIdx.x & 31;
    const int row = blockIdx.x * 8 + warp;
    const float* xr = g_x + (size_t)row * DMODEL;
    float vals[16];
    float s = 0.f;
    #pragma unroll
    for (int w = 0; w < 4; w++) {
        float4 t = *reinterpret_cast<const float4*>(xr + w * 128 + lane * 4);
        vals[w * 4 + 0] = t.x; vals[w * 4 + 1] = t.y;
        vals[w * 4 + 2] = t.z; vals[w * 4 + 3] = t.w;
        s += t.x + t.y + t.z + t.w;
    }
    #pragma unroll
    for (int o = 16; o > 0; o >>= 1) s += __shfl_xor_sync(0xffffffffu, s, o);
    const float mean = s * (1.0f / DMODEL);
    float sq = 0.f;
    #pragma unroll
    for (int i = 0; i < 16; i++) { float d = vals[i] - mean; sq += d * d; }
    #pragma unroll
    for (int o = 16; o > 0; o >>= 1) sq += __shfl_xor_sync(0xffffffffu, sq, o);
    const float rstd = rsqrtf(sq * (1.0f / DMODEL) + 1e-5f);
    bf16* hr = g_h + (size_t)row * DMODEL;
    #pragma unroll
    for (int w = 0; w < 4; w++) {
        float o0 = (vals[w * 4 + 0] - mean) * rstd * g[w * 128 + lane * 4 + 0] + bta[w * 128 + lane * 4 + 0];
        float o1 = (vals[w * 4 + 1] - mean) * rstd * g[w * 128 + lane * 4 + 1] + bta[w * 128 + lane * 4 + 1];
        float o2 = (vals[w * 4 + 2] - mean) * rstd * g[w * 128 + lane * 4 + 2] + bta[w * 128 + lane * 4 + 2];
        float o3 = (vals[w * 4 + 3] - mean) * rstd * g[w * 128 + lane * 4 + 3] + bta[w * 128 + lane * 4 + 3];
        *(__nv_bfloat162*)(hr + w * 128 + lane * 4)     = __nv_bfloat162(__float2bfloat16(o0), __float2bfloat16(o1));
        *(__nv_bfloat162*)(hr + w * 128 + lane * 4 + 2) = __nv_bfloat162(__float2bfloat16(o2), __float2bfloat16(o3));
    }
}

// ---------------- compositional attention: 4 CTAs per batch (2 heads each) ----------------
#define ATTN_SMEM_FLOATS (6656 + 5824 + 1716 + 1716 + 728 + 208 + 32 + 97)
__global__ void __launch_bounds__(256) attn_kernel(const float* __restrict__ score_w,
                                                   const float* __restrict__ score_b) {
    extern __shared__ float sm[];
    uint32_t* vsb = (uint32_t*)sm;       // 26*256 u32: v bf16x2, [k*512 + r*64 + d]
    float* wT   = sm + 6656;             // [j=208][q pad 28]
    float* qs   = wT + 5824;             // [26][66]
    float* ks   = qs + 1716;
    float* s    = ks + 1716;             // [26][28]
    float* vw   = s + 728;               // [208]
    float* qvd  = vw + 208;              // [26]
    float* sw   = qvd + 32;              // [97]
    float* scratch = qs;                 // 16*112 = 1792 <= 3432 (qs+ks)

    const int b = blockIdx.x >> 2;
    const int h0 = (blockIdx.x & 3) * 2;
    const int tid = threadIdx.x;

    if (tid < 96) sw[tid] = score_w[tid];
    if (tid == 96) sw[96] = score_b[0];

    // V: uint4 copies from qkvb (26*256 u32 = 1664 uint4)
    for (int i = tid; i < 26 * 64; i += 256) {
        const int row = i >> 6, cq = (i & 63) << 3;   // 8 bf16 per uint4
        *reinterpret_cast<uint4*>(vsb + row * 256 + (cq >> 1)) =
            *reinterpret_cast<const uint4*>(
                g_qkvb + ((size_t)b * 26 + row) * NQKV + 1024 + cq);
    }
    __syncthreads();

    for (int i = tid; i < 208; i += 256) {
        float acc = 0.f;
        #pragma unroll 8
        for (int dpp = 0; dpp < 32; dpp++) {
            const int dp = (dpp + i) & 31;
            const float2 v = bf2_to_f2(vsb[i * 32 + dp]);
            acc += v.x * sw[32 + dp * 2] + v.y * sw[32 + dp * 2 + 1];
        }
        vw[i] = acc;
    }
    __syncthreads();

    for (int hh = 0; hh < 2; hh++) {
        const int h = h0 + hh;
        for (int i = tid; i < 26 * 32; i += 256) {
            const int qi = i >> 5, dp = (i & 31) << 1;
            const float2 qv = bf2_to_f2(*reinterpret_cast<const uint32_t*>(
                g_qkvb + ((size_t)b * 26 + qi) * NQKV + h * 64 + dp));
            const float2 kv = bf2_to_f2(*reinterpret_cast<const uint32_t*>(
                g_qkvb + ((size_t)b * 26 + qi) * NQKV + 512 + h * 64 + dp));
            qs[qi * 66 + dp] = qv.x; qs[qi * 66 + dp + 1] = qv.y;
            ks[qi * 66 + dp] = kv.x; ks[qi * 66 + dp + 1] = kv.y;
        }
        __syncthreads();

        for (int i = tid; i < 338; i += 256) {
            const int qi = i / 13;
            const int k0 = (i % 13) * 2;
            u64t acc0 = 0ull, acc1 = 0ull;
            const float* qr = qs + qi * 66;
            const float* k0r = ks + k0 * 66;
            const float* k1r = k0r + 66;
            #pragma unroll 8
            for (int dp = 0; dp < 32; dp++) {
                const u64t qp  = *reinterpret_cast<const u64t*>(qr + 2 * dp);
                const u64t kp0 = *reinterpret_cast<const u64t*>(k0r + 2 * dp);
                const u64t kp1 = *reinterpret_cast<const u64t*>(k1r + 2 * dp);
                fma_x2(acc0, qp, kp0);
                fma_x2(acc1, qp, kp1);
            }
            const float2 a0 = unpack_ff(acc0);
            const float2 a1 = unpack_ff(acc1);
            s[qi * 28 + k0]     = (a0.x + a0.y) * 0.125f;
            s[qi * 28 + k0 + 1] = (a1.x + a1.y) * 0.125f;
        }
        if (tid < 26) {
            float acc = sw[96];
            #pragma unroll
            for (int j = 0; j < 32; j++)
                acc += __bfloat162float(g_qkvb[((size_t)b * 26 + tid) * NQKV + 1536 + h * 32 + j]) * sw[j];
            qvd[tid] = acc;
        }
        __syncthreads();

        if (tid < 26) {
            float mx = -1e30f;
            for (int k = 0; k < 26; k++) mx = fmaxf(mx, s[tid * 28 + k]);
            float sum = 0.f;
            for (int k = 0; k < 26; k++) {
                float e = expf(s[tid * 28 + k] - mx);
                s[tid * 28 + k] = e; sum += e;
            }
            float inv = 1.f / sum;
            for (int k = 0; k < 26; k++) s[tid * 28 + k] *= inv;
        }
        __syncthreads();

        // fused: comp logits + softmax-r (width-8 shfl) + wT write
        {
            const int qi_raw = tid >> 3;
            const int r = tid & 7;
            const int qi = (qi_raw < 26) ? qi_raw : 0;
            float acc = qvd[qi];
            #pragma unroll
            for (int k = 0; k < 26; k++) acc += s[qi * 28 + k] * vw[k * 8 + r];
            float mx = acc;
            #pragma unroll
            for (int o = 4; o > 0; o >>= 1)
                mx = fmaxf(mx, __shfl_xor_sync(0xffffffffu, mx, o, 8));
            float e = expf(acc - mx);
            float sum = e;
            #pragma unroll
            for (int o = 4; o > 0; o >>= 1)
                sum += __shfl_xor_sync(0xffffffffu, sum, o, 8);
            const float cval = e / sum;
            if (qi_raw < 26) {
                #pragma unroll
                for (int k = 0; k < 26; k++)
                    wT[(k * 8 + r) * 28 + qi_raw] = s[qi_raw * 28 + k] * cval;
            }
        }
        __syncthreads();

        // output phase 1
        u64t oac[4][2];
        #pragma unroll
        for (int a = 0; a < 4; a++) { oac[a][0] = 0ull; oac[a][1] = 0ull; }
        const int qg = tid >> 5;
        const int dq = ((tid >> 1) & 15) << 2;
        const int jh = tid & 1;
        if (tid < 224) {
            const int q0 = qg * 4;
            const int j0 = jh * 104;
            #pragma unroll 4
            for (int jj = 0; jj < 104; jj++) {
                const int j = j0 + jj;
                const float4 w4 = *reinterpret_cast<const float4*>(wT + j * 28 + q0);
                const u64t v01 = bf2_to_fx2(vsb[j * 32 + (dq >> 1)]);
                const u64t v23 = bf2_to_fx2(vsb[j * 32 + (dq >> 1) + 1]);
                const u64t w0 = pack_ff(w4.x, w4.x);
                const u64t w1 = pack_ff(w4.y, w4.y);
                const u64t w2 = pack_ff(w4.z, w4.z);
                const u64t w3 = pack_ff(w4.w, w4.w);
                fma_x2(oac[0][0], w0, v01); fma_x2(oac[0][1], w0, v23);
                fma_x2(oac[1][0], w1, v01); fma_x2(oac[1][1], w1, v23);
                fma_x2(oac[2][0], w2, v01); fma_x2(oac[2][1], w2, v23);
                fma_x2(oac[3][0], w3, v01); fma_x2(oac[3][1], w3, v23);
            }
        }
        float oacc[4][4];
        #pragma unroll
        for (int a = 0; a < 4; a++) {
            const float2 p01 = unpack_ff(oac[a][0]);
            const float2 p23 = unpack_ff(oac[a][1]);
            oacc[a][0] = p01.x; oacc[a][1] = p01.y;
            oacc[a][2] = p23.x; oacc[a][3] = p23.y;
        }
        if (tid < 224 && jh == 1) {
            const int idx = qg * 16 + (dq >> 2);
            #pragma unroll
            for (int a = 0; a < 4; a++)
                #pragma unroll
                for (int d2 = 0; d2 < 4; d2++)
                    scratch[(a * 4 + d2) * 112 + idx] = oacc[a][d2];
        }
        __syncthreads();

        if (tid < 224 && jh == 0) {
            const int idx = qg * 16 + (dq >> 2);
            const int q0 = qg * 4;
            #pragma unroll
            for (int a = 0; a < 4; a++) {
                const int q = q0 + a;
                if (q < 26) {
                    float r0 = oacc[a][0] + scratch[(a * 4 + 0) * 112 + idx];
                    float r1 = oacc[a][1] + scratch[(a * 4 + 1) * 112 + idx];
                    float r2 = oacc[a][2] + scratch[(a * 4 + 2) * 112 + idx];
                    float r3 = oacc[a][3] + scratch[(a * 4 + 3) * 112 + idx];
                    bf16* dst = g_o + ((size_t)b * 26 + q) * 512 + h * 64 + dq;
                    *(__nv_bfloat162*)(dst) =
                        __nv_bfloat162(__float2bfloat16(r0), __float2bfloat16(r1));
                    *(__nv_bfloat162*)(dst + 2) =
                        __nv_bfloat162(__float2bfloat16(r2), __float2bfloat16(r3));
                }
            }
        }
        __syncthreads();
    }
}

// ---------------- classifier + log_softmax ----------------
__global__ void __launch_bounds__(256) cls_kernel(const float* __restrict__ out_w,
                                                  const float* __restrict__ out_b,
                                                  float* __restrict__ out) {
    const int warp = threadIdx.x >> 5;
    const int lane = threadIdx.x & 31;
    const int b = blockIdx.x * 8 + warp;
    const float* xr = g_x + (size_t)b * SEQ * DMODEL;
    float acc[10] = {};
    for (int d = lane; d < DMODEL; d += 32) {
        float xv = xr[d];
        #pragma unroll
        for (int c = 0; c < 10; c++) acc[c] = fmaf(xv, out_w[d * 10 + c], acc[c]);
    }
    #pragma unroll
    for (int c = 0; c < 10; c++)
        #pragma unroll
        for (int o = 16; o > 0; o >>= 1)
            acc[c] += __shfl_xor_sync(0xffffffffu, acc[c], o);
    if (lane == 0) {
        float y[10], mx = -1e30f;
        #pragma unroll
        for (int c = 0; c < 10; c++) { y[c] = acc[c] + out_b[c]; mx = fmaxf(mx, y[c]); }
        float sum = 0.f;
        #pragma unroll
        for (int c = 0; c < 10; c++) sum += expf(y[c] - mx);
        float lse = logf(sum) + mx;
        #pragma unroll
        for (int c = 0; c < 10; c++) out[b * 10 + c] = y[c] - lse;
    }
}

// ---------------- host orchestration ----------------
extern "C" void kernel_launch(void* const* d_in, const int* in_sizes, int n_in,
                              void* d_out, int out_size) {
    const float* img      = (const float*)d_in[0];
    const float* qst      = (const float*)d_in[1];
    const float* conv_w   = (const float*)d_in[2];
    const float* conv_b   = (const float*)d_in[3];
    const float* qrep_w   = (const float*)d_in[4];
    const float* qrep_b   = (const float*)d_in[5];
    const float* cls_tok  = (const float*)d_in[6];
    const float* map_w    = (const float*)d_in[7];
    const float* map_b    = (const float*)d_in[8];
    const float* norm1_g  = (const float*)d_in[9];
    const float* norm1_b  = (const float*)d_in[10];
    const float* norm2_g  = (const float*)d_in[11];
    const float* norm2_b  = (const float*)d_in[12];
    const float* q_w      = (const float*)d_in[13];
    const float* q_b      = (const float*)d_in[14];
    const float* k_w      = (const float*)d_in[15];
    const float* k_b      = (const float*)d_in[16];
    const float* v_w      = (const float*)d_in[17];
    const float* v_b      = (const float*)d_in[18];
    const float* qv_w     = (const float*)d_in[19];
    const float* qv_b     = (const float*)d_in[20];
    const float* score_w  = (const float*)d_in[21];
    const float* score_b  = (const float*)d_in[22];
    const float* final_w  = (const float*)d_in[23];
    const float* final_b  = (const float*)d_in[24];
    const float* ffn1_w   = (const float*)d_in[25];
    const float* ffn1_b   = (const float*)d_in[26];
    const float* ffn2_w   = (const float*)d_in[27];
    const float* ffn2_b   = (const float*)d_in[28];
    const float* out_w    = (const float*)d_in[29];
    const float* out_b    = (const float*)d_in[30];

    bf16 *p_im2col, *p_wc, *p_mapT, *p_wqkv, *p_finalT,
         *p_ffn1T, *p_ffn2T, *p_xin, *p_h, *p_qkvb, *p_o, *p_t;
    float *p_bqkv, *p_pemb, *p_x;
    cudaGetSymbolAddress((void**)&p_im2col, g_im2col);
    cudaGetSymbolAddress((void**)&p_wc,     g_wc);
    cudaGetSymbolAddress((void**)&p_mapT,   g_mapT);
    cudaGetSymbolAddress((void**)&p_wqkv,   g_wqkv);
    cudaGetSymbolAddress((void**)&p_finalT, g_finalT);
    cudaGetSymbolAddress((void**)&p_ffn1T,  g_ffn1T);
    cudaGetSymbolAddress((void**)&p_ffn2T,  g_ffn2T);
    cudaGetSymbolAddress((void**)&p_xin,    g_xin);
    cudaGetSymbolAddress((void**)&p_h,      g_h);
    cudaGetSymbolAddress((void**)&p_qkvb,   g_qkvb);
    cudaGetSymbolAddress((void**)&p_o,      g_o);
    cudaGetSymbolAddress((void**)&p_t,      g_t);
    cudaGetSymbolAddress((void**)&p_bqkv,   g_bqkv);
    cudaGetSymbolAddress((void**)&p_pemb,   g_pemb);
    cudaGetSymbolAddress((void**)&p_x,      g_x);

    cudaFuncSetAttribute(gemm_tc, cudaFuncAttributeMaxDynamicSharedMemorySize, GEMM_SMEM_BYTES);
    cudaFuncSetAttribute(attn_kernel, cudaFuncAttributeMaxDynamicSharedMemorySize,
                         ATTN_SMEM_FLOATS * (int)sizeof(float));

    // ---- packing / front end ----
    packT_tiled_kernel<<<2432, 256>>>(q_w, k_w, v_w, qv_w, map_w, final_w, ffn1_w, ffn2_w);
    pack_small_kernel<<<736, 256>>>(conv_w, q_b, k_b, v_b, qv_b);
    que_kernel<<<BATCH, 256>>>(qst, qrep_w, qrep_b);
    im2col_kernel<<<BATCH * NPATCH, 128>>>(img);

    // conv: [6400,704] x [256,704]^T
    gemm_tc<<<dim3(2, 100), 256, GEMM_SMEM_BYTES>>>(
        p_im2col, p_wc, conv_b, nullptr, p_pemb, nullptr, 6400, HEMB, CONVKP, 0);
    assemble_kernel<<<NROWS, 256>>>(cls_tok);
    // map: [6656,512] x [512,512]^T
    gemm_tc<<<dim3(4, 104), 256, GEMM_SMEM_BYTES>>>(
        p_xin, p_mapT, map_b, nullptr, p_x, nullptr, NROWS, DMODEL, DMODEL, 0);

    // ---- 4 transformer iterations ----
    for (int it = 0; it < 4; it++) {
        ln_kernel<<<NROWS / 8, 256>>>(norm1_g, norm1_b);
        gemm_tc<<<dim3(14, 104), 256, GEMM_SMEM_BYTES>>>(
            p_h, p_wqkv, p_bqkv, nullptr, nullptr, p_qkvb, NROWS, NQKV, DMODEL, 3);
        attn_kernel<<<4 * BATCH, 256, ATTN_SMEM_FLOATS * (int)sizeof(float)>>>(score_w, score_b);
        gemm_tc<<<dim3(4, 104), 256, GEMM_SMEM_BYTES>>>(
            p_o, p_finalT, final_b, p_x, p_x, nullptr, NROWS, DMODEL, DMODEL, 2);
        ln_kernel<<<NROWS / 8, 256>>>(norm2_g, norm2_b);
        gemm_tc<<<dim3(8, 104), 256, GEMM_SMEM_BYTES>>>(
            p_h, p_ffn1T, ffn1_b, nullptr, nullptr, p_t, NROWS, 2 * DMODEL, DMODEL, 1);
        gemm_tc<<<dim3(4, 104), 256, GEMM_SMEM_BYTES>>>(
            p_t, p_ffn2T, ffn2_b, p_x, p_x, nullptr, NROWS, DMODEL, 2 * DMODEL, 2);
    }

    // ---- classifier ----
    cls_kernel<<<BATCH / 8, 256>>>(out_w, out_b, (float*)d_out);
}